// round 14
// baseline (speedup 1.0000x reference)
#include <cuda_runtime.h>
#include <cuda_bf16.h>
#include <cuda_fp16.h>
#include <cstdint>
#include <math.h>

#define E_    2048
#define HQ_   16
#define HK_   4
#define D_    128
#define KVE_  512
#define B_    2
#define N_    2048
#define MR_   (B_ * N_)   // 4096 rows

// ---------------- scratch (no allocations allowed) ----------------
__device__ __half s_q[(size_t)MR_ * E_];
__device__ __half s_k[(size_t)MR_ * E_];
__device__ __half s_v[(size_t)MR_ * E_];
__device__ __half w_q_h[(size_t)E_ * E_],   w_q_l[(size_t)E_ * E_];
__device__ __half w_k_h[(size_t)KVE_ * E_], w_k_l[(size_t)KVE_ * E_];
__device__ __half w_v_h[(size_t)KVE_ * E_], w_v_l[(size_t)KVE_ * E_];
__device__ __half w_o_h[(size_t)E_ * E_],   w_o_l[(size_t)E_ * E_];
__device__ __half q_h16[(size_t)MR_ * E_], q_l16[(size_t)MR_ * E_];
__device__ __half k_f16[(size_t)MR_ * KVE_];
__device__ __half v_f16[(size_t)MR_ * KVE_];
__device__ __half a_f16[(size_t)MR_ * E_];

// ================= helpers =================
__device__ __forceinline__ uint32_t smem_u32(const void* p) {
    uint32_t a;
    asm("{ .reg .u64 t; cvta.to.shared.u64 t, %1; cvt.u32.u64 %0, t; }" : "=r"(a) : "l"(p));
    return a;
}
__device__ __forceinline__ void cp16(uint32_t saddr, const void* g) {
    asm volatile("cp.async.cg.shared.global [%0], [%1], 16;" :: "r"(saddr), "l"(g));
}
#define CP_COMMIT() asm volatile("cp.async.commit_group;" ::: "memory")
#define CP_WAIT(n)  asm volatile("cp.async.wait_group %0;" :: "n"(n) : "memory")

__device__ __forceinline__ void ldm_x4(uint32_t* r, uint32_t addr) {
    asm volatile("ldmatrix.sync.aligned.m8n8.x4.shared.b16 {%0,%1,%2,%3}, [%4];"
                 : "=r"(r[0]), "=r"(r[1]), "=r"(r[2]), "=r"(r[3]) : "r"(addr));
}
__device__ __forceinline__ void ldm_x4_t(uint32_t* r, uint32_t addr) {
    asm volatile("ldmatrix.sync.aligned.m8n8.x4.trans.shared.b16 {%0,%1,%2,%3}, [%4];"
                 : "=r"(r[0]), "=r"(r[1]), "=r"(r[2]), "=r"(r[3]) : "r"(addr));
}
__device__ __forceinline__ void mma_f16(float* d, const uint32_t* a,
                                        uint32_t b0, uint32_t b1) {
    asm volatile(
        "mma.sync.aligned.m16n8k16.row.col.f32.f16.f16.f32 "
        "{%0,%1,%2,%3}, {%4,%5,%6,%7}, {%8,%9}, {%0,%1,%2,%3};"
        : "+f"(d[0]), "+f"(d[1]), "+f"(d[2]), "+f"(d[3])
        : "r"(a[0]), "r"(a[1]), "r"(a[2]), "r"(a[3]), "r"(b0), "r"(b1));
}
__device__ __forceinline__ void split_store2h(__half* hi, __half* lo,
                                              size_t off, float y0, float y1) {
    __half h0 = __float2half(y0);
    __half h1 = __float2half(y1);
    __half l0 = __float2half(y0 - __half2float(h0));
    __half l1 = __float2half(y1 - __half2float(h1));
    *(__half2*)(hi + off) = __halves2half2(h0, h1);
    *(__half2*)(lo + off) = __halves2half2(l0, l1);
}

// ========== fused convert: fp32 -> fp16 hi(/lo) over 7 segments ==========
struct SplitSegs {
    const float* x[7];
    __half* hi[7];
    __half* lo[7];
    int blk_end[7];
};

__global__ void split_fused(SplitSegs segs)
{
    int bid = blockIdx.x;
    int seg = 0;
    int base = 0;
#pragma unroll
    for (int s = 0; s < 7; s++) {
        if (bid >= segs.blk_end[s]) { seg = s + 1; base = segs.blk_end[s]; }
    }
    int i = (bid - base) * 256 + threadIdx.x;
    float4 v = ((const float4*)segs.x[seg])[i];
    __half h0 = __float2half(v.x);
    __half h1 = __float2half(v.y);
    __half h2 = __float2half(v.z);
    __half h3 = __float2half(v.w);
    __half* hi = segs.hi[seg];
    ((__half2*)hi)[i * 2]     = __halves2half2(h0, h1);
    ((__half2*)hi)[i * 2 + 1] = __halves2half2(h2, h3);
    __half* lo = segs.lo[seg];
    if (lo) {
        __half l0 = __float2half(v.x - __half2float(h0));
        __half l1 = __float2half(v.y - __half2float(h1));
        __half l2 = __float2half(v.z - __half2float(h2));
        __half l3 = __float2half(v.w - __half2float(h3));
        ((__half2*)lo)[i * 2]     = __halves2half2(l0, l1);
        ((__half2*)lo)[i * 2 + 1] = __halves2half2(l2, l3);
    }
}

// ====== HMMA NT GEMM core (fp16, B(weight)-split 2-term, 3-stage BK=32) ======
// 128 threads, 4 warps in 2x2 grid, 64x64 warp tiles (less smem duplication).
#define BM 128
#define BN 128
#define BK 32
#define LDSB 80
#define TILE_B (128 * LDSB)      // 10240
#define STAGE_B (3 * TILE_B)     // A, Bh, Bl = 30720
#define GSMEM (3 * STAGE_B)      // 92160 (3 stages)

__device__ __forceinline__ void load_chunk(uint32_t sb, int stage,
    const __half* __restrict__ Aa, const __half* __restrict__ Bh,
    const __half* __restrict__ Bl, int K, int tid)
{
    const __half* srcs[3] = { Aa, Bh, Bl };
    uint32_t base = sb + stage * STAGE_B;
#pragma unroll
    for (int t = 0; t < 3; t++) {
#pragma unroll
        for (int it = 0; it < 4; it++) {
            int idx = tid + it * 128;      // 0..511
            int r = idx >> 2;
            int c = idx & 3;
            cp16(base + t * TILE_B + r * LDSB + c * 16,
                 srcs[t] + (size_t)r * K + c * 8);
        }
    }
}

__device__ __forceinline__ void gemm_mainloop(
    uint32_t sb, const __half* pA, const __half* pBh, const __half* pBl,
    int K, int tid, int lane, int wm, int wn, float acc[4][8][4])
{
    const uint32_t a_off = (uint32_t)((lane & 15) * LDSB + (lane >> 4) * 16);
    const uint32_t b_off = (uint32_t)(((lane & 7) + (lane >> 4) * 8) * LDSB
                                      + ((lane >> 3) & 1) * 16);
    const int nch = K >> 5;

    load_chunk(sb, 0, pA, pBh, pBl, K, tid);
    CP_COMMIT();
    load_chunk(sb, 1, pA + BK, pBh + BK, pBl + BK, K, tid);
    CP_COMMIT();

    int cst = 0;
    int lst = 2;
    for (int c = 0; c < nch; c++) {
        if (c + 1 < nch) { CP_WAIT(1); } else { CP_WAIT(0); }
        __syncthreads();

        const uint32_t stb = sb + cst * STAGE_B;
        const uint32_t A_b  = stb + 0 * TILE_B;
        const uint32_t Bh_b = stb + 1 * TILE_B;
        const uint32_t Bl_b = stb + 2 * TILE_B;

#pragma unroll
        for (int ks = 0; ks < 2; ks++) {
            const uint32_t kbyte = ks * 32;
            uint32_t aS[4][4], bH[4][4], bL[4][4];
#pragma unroll
            for (int mi = 0; mi < 4; mi++)
                ldm_x4(aS[mi], A_b + (wm * 64 + mi * 16) * LDSB + kbyte + a_off);
#pragma unroll
            for (int ni = 0; ni < 4; ni++) {
                ldm_x4(bH[ni], Bh_b + (wn * 64 + ni * 16) * LDSB + kbyte + b_off);
                ldm_x4(bL[ni], Bl_b + (wn * 64 + ni * 16) * LDSB + kbyte + b_off);
            }
            // hi terms for all accumulators, then lo terms (per-acc order: hi, lo)
#pragma unroll
            for (int mi = 0; mi < 4; mi++)
#pragma unroll
                for (int nj = 0; nj < 8; nj++)
                    mma_f16(acc[mi][nj], aS[mi], bH[nj >> 1][(nj & 1) * 2],
                                                  bH[nj >> 1][(nj & 1) * 2 + 1]);
#pragma unroll
            for (int mi = 0; mi < 4; mi++)
#pragma unroll
                for (int nj = 0; nj < 8; nj++)
                    mma_f16(acc[mi][nj], aS[mi], bL[nj >> 1][(nj & 1) * 2],
                                                  bL[nj >> 1][(nj & 1) * 2 + 1]);
        }

        if (c + 2 < nch) {
            const size_t kb = (size_t)(c + 2) * BK;
            load_chunk(sb, lst, pA + kb, pBh + kb, pBl + kb, K, tid);
            CP_COMMIT();
        }
        cst = (cst == 2) ? 0 : cst + 1;
        lst = (lst == 2) ? 0 : lst + 1;
    }
}

// ---- fused Q/K/V projection GEMM (one launch) ----
__global__ void __launch_bounds__(128, 2) gemm_qkv(
    const __half* __restrict__ sq, const __half* __restrict__ wqh,
    const __half* __restrict__ wql, const float* __restrict__ bq,
    __half* __restrict__ qhp, __half* __restrict__ qlp,
    const __half* __restrict__ sk, const __half* __restrict__ wkh,
    const __half* __restrict__ wkl, const float* __restrict__ bk,
    __half* __restrict__ kfp,
    const __half* __restrict__ sv, const __half* __restrict__ wvh,
    const __half* __restrict__ wvl, const float* __restrict__ bv,
    __half* __restrict__ vfp)
{
    extern __shared__ char smem[];
    const uint32_t sb = smem_u32(smem);
    const int tid = threadIdx.x;
    const int lane = tid & 31;
    const int wid = tid >> 5;       // 0..3
    const int wm = wid >> 1;        // 0..1
    const int wn = wid & 1;         // 0..1

    const int bid = blockIdx.x;
    const int seg = (bid < 512) ? 0 : (bid < 640 ? 1 : 2);
    const int local = bid - (seg == 0 ? 0 : (seg == 1 ? 512 : 640));
    const int tilesX = (seg == 0) ? (E_ / BN) : (KVE_ / BN);
    const int m0 = (local / tilesX) * BM;
    const int n0 = (local % tilesX) * BN;

    const __half* Aa = (seg == 0) ? sq : (seg == 1 ? sk : sv);
    const __half* Bh = (seg == 0) ? wqh : (seg == 1 ? wkh : wvh);
    const __half* Bl = (seg == 0) ? wql : (seg == 1 ? wkl : wvl);
    const float* bias = (seg == 0) ? bq : (seg == 1 ? bk : bv);
    const int Nn = (seg == 0) ? E_ : KVE_;

    float acc[4][8][4];
#pragma unroll
    for (int i = 0; i < 4; i++)
#pragma unroll
        for (int j = 0; j < 8; j++)
#pragma unroll
            for (int q = 0; q < 4; q++) acc[i][j][q] = 0.f;

    gemm_mainloop(sb, Aa + (size_t)m0 * E_, Bh + (size_t)n0 * E_,
                  Bl + (size_t)n0 * E_, E_, tid, lane, wm, wn, acc);

    const int g = lane >> 2;
    const int cq = lane & 3;
#pragma unroll
    for (int mi = 0; mi < 4; mi++) {
#pragma unroll
        for (int nj = 0; nj < 8; nj++) {
            const int col = n0 + wn * 64 + nj * 8 + cq * 2;
            const float b0 = bias[col];
            const float b1 = bias[col + 1];
#pragma unroll
            for (int h = 0; h < 2; h++) {
                const int row = m0 + wm * 64 + mi * 16 + g + h * 8;
                const float y0 = acc[mi][nj][h * 2 + 0] + b0;
                const float y1 = acc[mi][nj][h * 2 + 1] + b1;
                const size_t off = (size_t)row * Nn + col;
                if (seg == 0)      split_store2h(qhp, qlp, off, y0, y1);
                else if (seg == 1) *(__half2*)(kfp + off) = __floats2half2_rn(y0, y1);
                else               *(__half2*)(vfp + off) = __floats2half2_rn(y0, y1);
            }
        }
    }
}

// ---- O projection GEMM (fp32 out) ----
__global__ void __launch_bounds__(128, 2) gemm_o(
    const __half* __restrict__ Aa, const __half* __restrict__ Bh,
    const __half* __restrict__ Bl,
    const float* __restrict__ bias, float* __restrict__ C)
{
    extern __shared__ char smem[];
    const uint32_t sb = smem_u32(smem);
    const int tid = threadIdx.x;
    const int lane = tid & 31;
    const int wid = tid >> 5;
    const int wm = wid >> 1;
    const int wn = wid & 1;
    const int m0 = blockIdx.y * BM;
    const int n0 = blockIdx.x * BN;

    float acc[4][8][4];
#pragma unroll
    for (int i = 0; i < 4; i++)
#pragma unroll
        for (int j = 0; j < 8; j++)
#pragma unroll
            for (int q = 0; q < 4; q++) acc[i][j][q] = 0.f;

    gemm_mainloop(sb, Aa + (size_t)m0 * E_, Bh + (size_t)n0 * E_,
                  Bl + (size_t)n0 * E_, E_, tid, lane, wm, wn, acc);

    const int g = lane >> 2;
    const int cq = lane & 3;
#pragma unroll
    for (int mi = 0; mi < 4; mi++) {
#pragma unroll
        for (int nj = 0; nj < 8; nj++) {
            const int col = n0 + wn * 64 + nj * 8 + cq * 2;
            const float b0 = bias[col];
            const float b1 = bias[col + 1];
#pragma unroll
            for (int h = 0; h < 2; h++) {
                const int row = m0 + wm * 64 + mi * 16 + g + h * 8;
                float2 v;
                v.x = acc[mi][nj][h * 2 + 0] + b0;
                v.y = acc[mi][nj][h * 2 + 1] + b1;
                *(float2*)(C + (size_t)row * E_ + col) = v;
            }
        }
    }
}

// =================================================================
// HMMA flash attention (R13): 64 q-rows/CTA, 128 threads, Q in regs,
// 3-stage KV, loads after compute, 2 CTAs/SM.
// =================================================================
#define QSTR 272
#define AT_STG  (2 * 64 * QSTR)        // 34816 (K, V)
#define AT_K    0
#define AT_V    (64 * QSTR)
#define AT_SMEM (3 * AT_STG)           // 104448 -> 2 CTAs/SM

__device__ __forceinline__ void attn_load_kv(uint32_t sb, int stage, int b, int hk,
                                             int kt, const __half* kf,
                                             const __half* vf, int tid)
{
    const uint32_t base = sb + stage * AT_STG;
    const size_t rowg = (size_t)(b * N_ + kt * 64);
#pragma unroll
    for (int it = 0; it < 16; it++) {
        int idx = tid + it * 128;              // 0..2047
        int buf = idx >> 10;                   // 0: K, 1: V
        int r = (idx & 1023) >> 4;             // 0..63
        int c = idx & 15;
        uint32_t dst = base + (buf ? AT_V : AT_K) + r * QSTR + c * 16;
        const __half* src = buf ? vf : kf;
        cp16(dst, src + (rowg + r) * KVE_ + hk * D_ + c * 8);
    }
}

__global__ void __launch_bounds__(128, 2) attn_mma(
    const __half* __restrict__ qh, const __half* __restrict__ ql,
    const __half* __restrict__ kf, const __half* __restrict__ vf,
    __half* __restrict__ ao,
    const int* __restrict__ causal_p)
{
    extern __shared__ char smem[];
    const uint32_t sb = smem_u32(smem);
    const int tid = threadIdx.x;
    const int lane = tid & 31;
    const int wid = tid >> 5;
    const int qt = (int)(gridDim.x - 1 - blockIdx.x);  // heavy tiles first
    const int bh = blockIdx.y;
    const int b  = bh >> 4;
    const int hq = bh & 15;
    const int hk = hq >> 2;
    const int wr = wid * 16;
    const int g = lane >> 2;
    const int cq = lane & 3;
    const bool causal = (causal_p[0] != 0);
    const float lscale = 0.08838834764831845f;  // 1/sqrt(128)

    const uint32_t a_off = (uint32_t)((lane & 15) * QSTR + (lane >> 4) * 16);
    const uint32_t b_off = (uint32_t)(((lane & 7) + (lane >> 4) * 8) * QSTR
                                      + ((lane >> 3) & 1) * 16);

    const int ktend = causal ? (qt + 1) : (N_ / 64);

    // ---- prologue A: stage Q tile (hi+lo) through stages 0/1 smem ----
    {
        const size_t rowg = (size_t)(b * N_ + qt * 64);
#pragma unroll
        for (int it = 0; it < 16; it++) {
            int idx = tid + it * 128;
            int buf = idx >> 10;
            int r = (idx & 1023) >> 4;
            int c = idx & 15;
            uint32_t dst = sb + buf * AT_STG + r * QSTR + c * 16;
            const __half* src = buf ? ql : qh;
            cp16(dst, src + (rowg + r) * E_ + hq * D_ + c * 8);
        }
    }
    CP_COMMIT();
    CP_WAIT(0);
    __syncthreads();

    uint32_t qHf[8][4], qLf[8][4];
#pragma unroll
    for (int ks = 0; ks < 8; ks++) {
        ldm_x4(qHf[ks], sb + 0 * AT_STG + wr * QSTR + ks * 32 + a_off);
        ldm_x4(qLf[ks], sb + 1 * AT_STG + wr * QSTR + ks * 32 + a_off);
    }
    __syncthreads();

    attn_load_kv(sb, 0, b, hk, 0, kf, vf, tid);
    CP_COMMIT();
    if (1 < ktend) {
        attn_load_kv(sb, 1, b, hk, 1, kf, vf, tid);
        CP_COMMIT();
    }

    float m_i[2] = { -1e30f, -1e30f };
    float l_i[2] = { 0.f, 0.f };
    float o[16][4];
#pragma unroll
    for (int i = 0; i < 16; i++)
#pragma unroll
        for (int j = 0; j < 4; j++) o[i][j] = 0.f;

    for (int kt = 0; kt < ktend; kt++) {
        if (kt + 1 < ktend) { CP_WAIT(1); } else { CP_WAIT(0); }
        __syncthreads();

        const int cst = kt % 3;
        const uint32_t Kb = sb + cst * AT_STG + AT_K;
        const uint32_t Vb = sb + cst * AT_STG + AT_V;

        float s[8][4];
#pragma unroll
        for (int i = 0; i < 8; i++)
#pragma unroll
            for (int j = 0; j < 4; j++) s[i][j] = 0.f;

#pragma unroll
        for (int ks = 0; ks < 8; ks++) {
            const uint32_t kb = ks * 32;
#pragma unroll
            for (int t = 0; t < 4; t++) {
                uint32_t b4[4];
                ldm_x4(b4, Kb + (t * 16) * QSTR + kb + b_off);
                mma_f16(s[2 * t],     qHf[ks], b4[0], b4[1]);
                mma_f16(s[2 * t],     qLf[ks], b4[0], b4[1]);
                mma_f16(s[2 * t + 1], qHf[ks], b4[2], b4[3]);
                mma_f16(s[2 * t + 1], qLf[ks], b4[2], b4[3]);
            }
        }

#pragma unroll
        for (int ni = 0; ni < 8; ni++)
#pragma unroll
            for (int j = 0; j < 4; j++) s[ni][j] *= lscale;

        const int row0 = qt * 64 + wr + g;
        if (causal && (kt * 64 + 63 > qt * 64 + wr)) {
            const int col0 = kt * 64 + 2 * cq;
#pragma unroll
            for (int ni = 0; ni < 8; ni++)
#pragma unroll
                for (int j = 0; j < 4; j++) {
                    int row = row0 + (j >> 1) * 8;
                    int col = col0 + ni * 8 + (j & 1);
                    if (col > row) s[ni][j] = -1e30f;
                }
        }

#pragma unroll
        for (int h = 0; h < 2; h++) {
            float rm = -1e30f;
#pragma unroll
            for (int ni = 0; ni < 8; ni++)
                rm = fmaxf(rm, fmaxf(s[ni][2 * h], s[ni][2 * h + 1]));
            rm = fmaxf(rm, __shfl_xor_sync(0xffffffffu, rm, 1));
            rm = fmaxf(rm, __shfl_xor_sync(0xffffffffu, rm, 2));
            const float mn = fmaxf(m_i[h], rm);
            const float alpha = __expf(m_i[h] - mn);
            m_i[h] = mn;
            float rs = 0.f;
#pragma unroll
            for (int ni = 0; ni < 8; ni++) {
                float e0 = __expf(s[ni][2 * h]     - mn);
                float e1 = __expf(s[ni][2 * h + 1] - mn);
                s[ni][2 * h] = e0; s[ni][2 * h + 1] = e1;
                rs += e0 + e1;
            }
            rs += __shfl_xor_sync(0xffffffffu, rs, 1);
            rs += __shfl_xor_sync(0xffffffffu, rs, 2);
            l_i[h] = l_i[h] * alpha + rs;
#pragma unroll
            for (int np = 0; np < 16; np++) {
                o[np][2 * h]     *= alpha;
                o[np][2 * h + 1] *= alpha;
            }
        }

#pragma unroll
        for (int ks = 0; ks < 4; ks++) {
            uint32_t aPh[4], aPl[4];
#pragma unroll
            for (int q = 0; q < 4; q++) {
                const int ni = 2 * ks + (q >> 1);
                const int j0 = (q & 1) * 2;
                float e0 = s[ni][j0], e1 = s[ni][j0 + 1];
                __half2 hh = __floats2half2_rn(e0, e1);
                aPh[q] = *(uint32_t*)&hh;
                float2 hf = __half22float2(hh);
                __half2 ll = __floats2half2_rn(e0 - hf.x, e1 - hf.y);
                aPl[q] = *(uint32_t*)&ll;
            }
#pragma unroll
            for (int np = 0; np < 8; np++) {
                uint32_t bv[4];
                ldm_x4_t(bv, Vb + (ks * 16) * QSTR + np * 32 + a_off);
                mma_f16(o[2 * np],     aPh, bv[0], bv[1]);
                mma_f16(o[2 * np],     aPl, bv[0], bv[1]);
                mma_f16(o[2 * np + 1], aPh, bv[2], bv[3]);
                mma_f16(o[2 * np + 1], aPl, bv[2], bv[3]);
            }
        }

        if (kt + 2 < ktend) {
            attn_load_kv(sb, (kt + 2) % 3, b, hk, kt + 2, kf, vf, tid);
            CP_COMMIT();
        }
    }

    const float inv0 = 1.f / l_i[0];
    const float inv1 = 1.f / l_i[1];
    const size_t rowa = (size_t)(b * N_ + qt * 64 + wr + g);
    const int colb = hq * D_ + 2 * cq;
#pragma unroll
    for (int np = 0; np < 16; np++) {
        *(__half2*)(ao + rowa * E_ + colb + np * 8) =
            __floats2half2_rn(o[np][0] * inv0, o[np][1] * inv0);
        *(__half2*)(ao + (rowa + 8) * E_ + colb + np * 8) =
            __floats2half2_rn(o[np][2] * inv1, o[np][3] * inv1);
    }
}

// =================================================================
extern "C" void kernel_launch(void* const* d_in, const int* in_sizes, int n_in,
                              void* d_out, int out_size)
{
    const float* query = (const float*)d_in[0];
    const float* key   = (const float*)d_in[1];
    const float* value = (const float*)d_in[2];
    const float* Wq = (const float*)d_in[3];
    const float* bq = (const float*)d_in[4];
    const float* Wk = (const float*)d_in[5];
    const float* bk = (const float*)d_in[6];
    const float* Wv = (const float*)d_in[7];
    const float* bv = (const float*)d_in[8];
    const float* Wo = (const float*)d_in[9];
    const float* bo = (const float*)d_in[10];
    const int* is_causal = (const int*)d_in[11];
    float* out = (float*)d_out;

    __half *sq, *sk, *sv;
    __half *wqh, *wql, *wkh, *wkl, *wvh, *wvl, *woh, *wol;
    __half *qhp, *qlp, *kfp, *vfp, *afp;
    cudaGetSymbolAddress((void**)&sq, s_q);
    cudaGetSymbolAddress((void**)&sk, s_k);
    cudaGetSymbolAddress((void**)&sv, s_v);
    cudaGetSymbolAddress((void**)&wqh, w_q_h);  cudaGetSymbolAddress((void**)&wql, w_q_l);
    cudaGetSymbolAddress((void**)&wkh, w_k_h);  cudaGetSymbolAddress((void**)&wkl, w_k_l);
    cudaGetSymbolAddress((void**)&wvh, w_v_h);  cudaGetSymbolAddress((void**)&wvl, w_v_l);
    cudaGetSymbolAddress((void**)&woh, w_o_h);  cudaGetSymbolAddress((void**)&wol, w_o_l);
    cudaGetSymbolAddress((void**)&qhp, q_h16);  cudaGetSymbolAddress((void**)&qlp, q_l16);
    cudaGetSymbolAddress((void**)&kfp, k_f16);  cudaGetSymbolAddress((void**)&vfp, v_f16);
    cudaGetSymbolAddress((void**)&afp, a_f16);

    // ---- fused converts (7 segments, one launch) ----
    const int actN4 = (MR_ * E_) / 4;
    const int wqN4  = (E_ * E_) / 4;
    const int wkN4  = (KVE_ * E_) / 4;
    SplitSegs segs;
    segs.x[0] = query; segs.hi[0] = sq;  segs.lo[0] = nullptr;
    segs.x[1] = key;   segs.hi[1] = sk;  segs.lo[1] = nullptr;
    segs.x[2] = value; segs.hi[2] = sv;  segs.lo[2] = nullptr;
    segs.x[3] = Wq;    segs.hi[3] = wqh; segs.lo[3] = wql;
    segs.x[4] = Wk;    segs.hi[4] = wkh; segs.lo[4] = wkl;
    segs.x[5] = Wv;    segs.hi[5] = wvh; segs.lo[5] = wvl;
    segs.x[6] = Wo;    segs.hi[6] = woh; segs.lo[6] = wol;
    int nb = 0;
    const int segBlocks[7] = { actN4/256, actN4/256, actN4/256,
                               wqN4/256, wkN4/256, wkN4/256, wqN4/256 };
    for (int s = 0; s < 7; s++) { nb += segBlocks[s]; segs.blk_end[s] = nb; }
    split_fused<<<nb, 256>>>(segs);

    // ---- fused Q/K/V projection GEMMs (128-thread CTAs) ----
    cudaFuncSetAttribute(gemm_qkv, cudaFuncAttributeMaxDynamicSharedMemorySize, GSMEM);
    cudaFuncSetAttribute(gemm_o,   cudaFuncAttributeMaxDynamicSharedMemorySize, GSMEM);
    const int qkvBlocks = (E_ / BN) * (MR_ / BM) + 2 * (KVE_ / BN) * (MR_ / BM); // 768
    gemm_qkv<<<qkvBlocks, 128, GSMEM>>>(
        sq, wqh, wql, bq, qhp, qlp,
        sk, wkh, wkl, bk, kfp,
        sv, wvh, wvl, bv, vfp);

    // ---- HMMA flash attention ----
    cudaFuncSetAttribute(attn_mma, cudaFuncAttributeMaxDynamicSharedMemorySize, AT_SMEM);
    attn_mma<<<dim3(N_ / 64, B_ * HQ_), 128, AT_SMEM>>>(
        qhp, qlp, kfp, vfp, afp, is_causal);

    // ---- O projection (fp32 out) ----
    gemm_o<<<dim3(E_ / BN, MR_ / BM), 128, GSMEM>>>(afp, woh, wol, bo, out);
}

// round 15
// speedup vs baseline: 1.0823x; 1.0823x over previous
#include <cuda_runtime.h>
#include <cuda_bf16.h>
#include <cuda_fp16.h>
#include <cstdint>
#include <math.h>

#define E_    2048
#define HQ_   16
#define HK_   4
#define D_    128
#define KVE_  512
#define B_    2
#define N_    2048
#define MR_   (B_ * N_)   // 4096 rows

// ---------------- scratch (no allocations allowed) ----------------
__device__ __half s_q[(size_t)MR_ * E_];
__device__ __half s_k[(size_t)MR_ * E_];
__device__ __half s_v[(size_t)MR_ * E_];
__device__ __half w_q_h[(size_t)E_ * E_],   w_q_l[(size_t)E_ * E_];
__device__ __half w_k_h[(size_t)KVE_ * E_], w_k_l[(size_t)KVE_ * E_];
__device__ __half w_v_h[(size_t)KVE_ * E_], w_v_l[(size_t)KVE_ * E_];
__device__ __half w_o_h[(size_t)E_ * E_],   w_o_l[(size_t)E_ * E_];
__device__ __half q_h16[(size_t)MR_ * E_], q_l16[(size_t)MR_ * E_];
__device__ __half k_f16[(size_t)MR_ * KVE_];
__device__ __half v_f16[(size_t)MR_ * KVE_];
__device__ __half a_f16[(size_t)MR_ * E_];

// ================= helpers =================
__device__ __forceinline__ uint32_t smem_u32(const void* p) {
    uint32_t a;
    asm("{ .reg .u64 t; cvta.to.shared.u64 t, %1; cvt.u32.u64 %0, t; }" : "=r"(a) : "l"(p));
    return a;
}
__device__ __forceinline__ void cp16(uint32_t saddr, const void* g) {
    asm volatile("cp.async.cg.shared.global [%0], [%1], 16;" :: "r"(saddr), "l"(g));
}
#define CP_COMMIT() asm volatile("cp.async.commit_group;" ::: "memory")
#define CP_WAIT(n)  asm volatile("cp.async.wait_group %0;" :: "n"(n) : "memory")

__device__ __forceinline__ void ldm_x4(uint32_t* r, uint32_t addr) {
    asm volatile("ldmatrix.sync.aligned.m8n8.x4.shared.b16 {%0,%1,%2,%3}, [%4];"
                 : "=r"(r[0]), "=r"(r[1]), "=r"(r[2]), "=r"(r[3]) : "r"(addr));
}
__device__ __forceinline__ void ldm_x4_t(uint32_t* r, uint32_t addr) {
    asm volatile("ldmatrix.sync.aligned.m8n8.x4.trans.shared.b16 {%0,%1,%2,%3}, [%4];"
                 : "=r"(r[0]), "=r"(r[1]), "=r"(r[2]), "=r"(r[3]) : "r"(addr));
}
__device__ __forceinline__ void mma_f16(float* d, const uint32_t* a,
                                        uint32_t b0, uint32_t b1) {
    asm volatile(
        "mma.sync.aligned.m16n8k16.row.col.f32.f16.f16.f32 "
        "{%0,%1,%2,%3}, {%4,%5,%6,%7}, {%8,%9}, {%0,%1,%2,%3};"
        : "+f"(d[0]), "+f"(d[1]), "+f"(d[2]), "+f"(d[3])
        : "r"(a[0]), "r"(a[1]), "r"(a[2]), "r"(a[3]), "r"(b0), "r"(b1));
}
__device__ __forceinline__ void split_store2h(__half* hi, __half* lo,
                                              size_t off, float y0, float y1) {
    __half h0 = __float2half(y0);
    __half h1 = __float2half(y1);
    __half l0 = __float2half(y0 - __half2float(h0));
    __half l1 = __float2half(y1 - __half2float(h1));
    *(__half2*)(hi + off) = __halves2half2(h0, h1);
    *(__half2*)(lo + off) = __halves2half2(l0, l1);
}

// ========== fused convert: fp32 -> fp16 hi(/lo) over 7 segments ==========
struct SplitSegs {
    const float* x[7];
    __half* hi[7];
    __half* lo[7];
    int blk_end[7];
};

__global__ void split_fused(SplitSegs segs)
{
    int bid = blockIdx.x;
    int seg = 0;
    int base = 0;
#pragma unroll
    for (int s = 0; s < 7; s++) {
        if (bid >= segs.blk_end[s]) { seg = s + 1; base = segs.blk_end[s]; }
    }
    int i = (bid - base) * 256 + threadIdx.x;
    float4 v = ((const float4*)segs.x[seg])[i];
    __half h0 = __float2half(v.x);
    __half h1 = __float2half(v.y);
    __half h2 = __float2half(v.z);
    __half h3 = __float2half(v.w);
    __half* hi = segs.hi[seg];
    ((__half2*)hi)[i * 2]     = __halves2half2(h0, h1);
    ((__half2*)hi)[i * 2 + 1] = __halves2half2(h2, h3);
    __half* lo = segs.lo[seg];
    if (lo) {
        __half l0 = __float2half(v.x - __half2float(h0));
        __half l1 = __float2half(v.y - __half2float(h1));
        __half l2 = __float2half(v.z - __half2float(h2));
        __half l3 = __float2half(v.w - __half2float(h3));
        ((__half2*)lo)[i * 2]     = __halves2half2(l0, l1);
        ((__half2*)lo)[i * 2 + 1] = __halves2half2(l2, l3);
    }
}

// ====== HMMA NT GEMM core (fp16, B(weight)-split 2-term, 3-stage BK=32) ======
// R11 config; cp.async issue moved to mid-compute (between ks=0 and ks=1).
#define BM 128
#define BN 128
#define BK 32
#define LDSB 80
#define TILE_B (128 * LDSB)      // 10240
#define STAGE_B (3 * TILE_B)     // A, Bh, Bl = 30720
#define GSMEM (3 * STAGE_B)      // 92160 (3 stages)

__device__ __forceinline__ void load_chunk(uint32_t sb, int stage,
    const __half* __restrict__ Aa, const __half* __restrict__ Bh,
    const __half* __restrict__ Bl, int K, int tid)
{
    const __half* srcs[3] = { Aa, Bh, Bl };
    uint32_t base = sb + stage * STAGE_B;
#pragma unroll
    for (int t = 0; t < 3; t++) {
#pragma unroll
        for (int it = 0; it < 2; it++) {
            int idx = tid + it * 256;
            int r = idx >> 2;
            int c = idx & 3;
            cp16(base + t * TILE_B + r * LDSB + c * 16,
                 srcs[t] + (size_t)r * K + c * 8);
        }
    }
}

__device__ __forceinline__ void gemm_mainloop(
    uint32_t sb, const __half* pA, const __half* pBh, const __half* pBl,
    int K, int tid, int lane, int wm, int wn, float acc[4][4][4])
{
    const uint32_t a_off = (uint32_t)((lane & 15) * LDSB + (lane >> 4) * 16);
    const uint32_t b_off = (uint32_t)(((lane & 7) + (lane >> 4) * 8) * LDSB
                                      + ((lane >> 3) & 1) * 16);
    const int nch = K >> 5;

    load_chunk(sb, 0, pA, pBh, pBl, K, tid);
    CP_COMMIT();
    load_chunk(sb, 1, pA + BK, pBh + BK, pBl + BK, K, tid);
    CP_COMMIT();

    int cst = 0;
    int lst = 2;
    for (int c = 0; c < nch; c++) {
        if (c + 1 < nch) { CP_WAIT(1); } else { CP_WAIT(0); }
        __syncthreads();

        const uint32_t stb = sb + cst * STAGE_B;
        const uint32_t A_b  = stb + 0 * TILE_B;
        const uint32_t Bh_b = stb + 1 * TILE_B;
        const uint32_t Bl_b = stb + 2 * TILE_B;

#pragma unroll
        for (int ks = 0; ks < 2; ks++) {
            const uint32_t kbyte = ks * 32;
            uint32_t aS[4][4], bH[2][4], bL[2][4];
#pragma unroll
            for (int mi = 0; mi < 4; mi++)
                ldm_x4(aS[mi], A_b + (wm * 64 + mi * 16) * LDSB + kbyte + a_off);
#pragma unroll
            for (int nb = 0; nb < 2; nb++) {
                ldm_x4(bH[nb], Bh_b + (wn * 32 + nb * 16) * LDSB + kbyte + b_off);
                ldm_x4(bL[nb], Bl_b + (wn * 32 + nb * 16) * LDSB + kbyte + b_off);
            }
#pragma unroll
            for (int mi = 0; mi < 4; mi++)
#pragma unroll
                for (int ni = 0; ni < 4; ni++)
                    mma_f16(acc[mi][ni], aS[mi], bH[ni >> 1][(ni & 1) * 2],
                                                  bH[ni >> 1][(ni & 1) * 2 + 1]);
#pragma unroll
            for (int mi = 0; mi < 4; mi++)
#pragma unroll
                for (int ni = 0; ni < 4; ni++)
                    mma_f16(acc[mi][ni], aS[mi], bL[ni >> 1][(ni & 1) * 2],
                                                  bL[ni >> 1][(ni & 1) * 2 + 1]);

            // mid-compute load issue: after ks=0's MMA stream is in flight
            if (ks == 0 && c + 2 < nch) {
                const size_t kb = (size_t)(c + 2) * BK;
                load_chunk(sb, lst, pA + kb, pBh + kb, pBl + kb, K, tid);
                CP_COMMIT();
            }
        }
        cst = (cst == 2) ? 0 : cst + 1;
        lst = (lst == 2) ? 0 : lst + 1;
    }
}

// ---- fused Q/K/V projection GEMM (one launch) ----
__global__ void __launch_bounds__(256, 2) gemm_qkv(
    const __half* __restrict__ sq, const __half* __restrict__ wqh,
    const __half* __restrict__ wql, const float* __restrict__ bq,
    __half* __restrict__ qhp, __half* __restrict__ qlp,
    const __half* __restrict__ sk, const __half* __restrict__ wkh,
    const __half* __restrict__ wkl, const float* __restrict__ bk,
    __half* __restrict__ kfp,
    const __half* __restrict__ sv, const __half* __restrict__ wvh,
    const __half* __restrict__ wvl, const float* __restrict__ bv,
    __half* __restrict__ vfp)
{
    extern __shared__ char smem[];
    const uint32_t sb = smem_u32(smem);
    const int tid = threadIdx.x;
    const int lane = tid & 31;
    const int wid = tid >> 5;
    const int wm = wid & 1;
    const int wn = wid >> 1;

    const int bid = blockIdx.x;
    const int seg = (bid < 512) ? 0 : (bid < 640 ? 1 : 2);
    const int local = bid - (seg == 0 ? 0 : (seg == 1 ? 512 : 640));
    const int tilesX = (seg == 0) ? (E_ / BN) : (KVE_ / BN);
    const int m0 = (local / tilesX) * BM;
    const int n0 = (local % tilesX) * BN;

    const __half* Aa = (seg == 0) ? sq : (seg == 1 ? sk : sv);
    const __half* Bh = (seg == 0) ? wqh : (seg == 1 ? wkh : wvh);
    const __half* Bl = (seg == 0) ? wql : (seg == 1 ? wkl : wvl);
    const float* bias = (seg == 0) ? bq : (seg == 1 ? bk : bv);
    const int Nn = (seg == 0) ? E_ : KVE_;

    float acc[4][4][4];
#pragma unroll
    for (int i = 0; i < 4; i++)
#pragma unroll
        for (int j = 0; j < 4; j++)
#pragma unroll
            for (int q = 0; q < 4; q++) acc[i][j][q] = 0.f;

    gemm_mainloop(sb, Aa + (size_t)m0 * E_, Bh + (size_t)n0 * E_,
                  Bl + (size_t)n0 * E_, E_, tid, lane, wm, wn, acc);

    const int g = lane >> 2;
    const int cq = lane & 3;
#pragma unroll
    for (int mi = 0; mi < 4; mi++) {
#pragma unroll
        for (int ni = 0; ni < 4; ni++) {
            const int col = n0 + wn * 32 + ni * 8 + cq * 2;
            const float b0 = bias[col];
            const float b1 = bias[col + 1];
#pragma unroll
            for (int h = 0; h < 2; h++) {
                const int row = m0 + wm * 64 + mi * 16 + g + h * 8;
                const float y0 = acc[mi][ni][h * 2 + 0] + b0;
                const float y1 = acc[mi][ni][h * 2 + 1] + b1;
                const size_t off = (size_t)row * Nn + col;
                if (seg == 0)      split_store2h(qhp, qlp, off, y0, y1);
                else if (seg == 1) *(__half2*)(kfp + off) = __floats2half2_rn(y0, y1);
                else               *(__half2*)(vfp + off) = __floats2half2_rn(y0, y1);
            }
        }
    }
}

// ---- O projection GEMM (fp32 out) ----
__global__ void __launch_bounds__(256, 2) gemm_o(
    const __half* __restrict__ Aa, const __half* __restrict__ Bh,
    const __half* __restrict__ Bl,
    const float* __restrict__ bias, float* __restrict__ C)
{
    extern __shared__ char smem[];
    const uint32_t sb = smem_u32(smem);
    const int tid = threadIdx.x;
    const int lane = tid & 31;
    const int wid = tid >> 5;
    const int wm = wid & 1;
    const int wn = wid >> 1;
    const int m0 = blockIdx.y * BM;
    const int n0 = blockIdx.x * BN;

    float acc[4][4][4];
#pragma unroll
    for (int i = 0; i < 4; i++)
#pragma unroll
        for (int j = 0; j < 4; j++)
#pragma unroll
            for (int q = 0; q < 4; q++) acc[i][j][q] = 0.f;

    gemm_mainloop(sb, Aa + (size_t)m0 * E_, Bh + (size_t)n0 * E_,
                  Bl + (size_t)n0 * E_, E_, tid, lane, wm, wn, acc);

    const int g = lane >> 2;
    const int cq = lane & 3;
#pragma unroll
    for (int mi = 0; mi < 4; mi++) {
#pragma unroll
        for (int ni = 0; ni < 4; ni++) {
            const int col = n0 + wn * 32 + ni * 8 + cq * 2;
            const float b0 = bias[col];
            const float b1 = bias[col + 1];
#pragma unroll
            for (int h = 0; h < 2; h++) {
                const int row = m0 + wm * 64 + mi * 16 + g + h * 8;
                float2 v;
                v.x = acc[mi][ni][h * 2 + 0] + b0;
                v.y = acc[mi][ni][h * 2 + 1] + b1;
                *(float2*)(C + (size_t)row * E_ + col) = v;
            }
        }
    }
}

// =================================================================
// HMMA flash attention: 64 q-rows/CTA, 128 threads, Q in regs,
// 3-stage KV, mid-compute load issue (between softmax and PV), 2 CTAs/SM.
// =================================================================
#define QSTR 272
#define AT_STG  (2 * 64 * QSTR)        // 34816 (K, V)
#define AT_K    0
#define AT_V    (64 * QSTR)
#define AT_SMEM (3 * AT_STG)           // 104448 -> 2 CTAs/SM

__device__ __forceinline__ void attn_load_kv(uint32_t sb, int stage, int b, int hk,
                                             int kt, const __half* kf,
                                             const __half* vf, int tid)
{
    const uint32_t base = sb + stage * AT_STG;
    const size_t rowg = (size_t)(b * N_ + kt * 64);
#pragma unroll
    for (int it = 0; it < 16; it++) {
        int idx = tid + it * 128;              // 0..2047
        int buf = idx >> 10;                   // 0: K, 1: V
        int r = (idx & 1023) >> 4;             // 0..63
        int c = idx & 15;
        uint32_t dst = base + (buf ? AT_V : AT_K) + r * QSTR + c * 16;
        const __half* src = buf ? vf : kf;
        cp16(dst, src + (rowg + r) * KVE_ + hk * D_ + c * 8);
    }
}

__global__ void __launch_bounds__(128, 2) attn_mma(
    const __half* __restrict__ qh, const __half* __restrict__ ql,
    const __half* __restrict__ kf, const __half* __restrict__ vf,
    __half* __restrict__ ao,
    const int* __restrict__ causal_p)
{
    extern __shared__ char smem[];
    const uint32_t sb = smem_u32(smem);
    const int tid = threadIdx.x;
    const int lane = tid & 31;
    const int wid = tid >> 5;
    const int qt = (int)(gridDim.x - 1 - blockIdx.x);  // heavy tiles first
    const int bh = blockIdx.y;
    const int b  = bh >> 4;
    const int hq = bh & 15;
    const int hk = hq >> 2;
    const int wr = wid * 16;
    const int g = lane >> 2;
    const int cq = lane & 3;
    const bool causal = (causal_p[0] != 0);
    const float lscale = 0.08838834764831845f;  // 1/sqrt(128)

    const uint32_t a_off = (uint32_t)((lane & 15) * QSTR + (lane >> 4) * 16);
    const uint32_t b_off = (uint32_t)(((lane & 7) + (lane >> 4) * 8) * QSTR
                                      + ((lane >> 3) & 1) * 16);

    const int ktend = causal ? (qt + 1) : (N_ / 64);

    // ---- prologue A: stage Q tile (hi+lo) through stages 0/1 smem ----
    {
        const size_t rowg = (size_t)(b * N_ + qt * 64);
#pragma unroll
        for (int it = 0; it < 16; it++) {
            int idx = tid + it * 128;
            int buf = idx >> 10;
            int r = (idx & 1023) >> 4;
            int c = idx & 15;
            uint32_t dst = sb + buf * AT_STG + r * QSTR + c * 16;
            const __half* src = buf ? ql : qh;
            cp16(dst, src + (rowg + r) * E_ + hq * D_ + c * 8);
        }
    }
    CP_COMMIT();
    CP_WAIT(0);
    __syncthreads();

    uint32_t qHf[8][4], qLf[8][4];
#pragma unroll
    for (int ks = 0; ks < 8; ks++) {
        ldm_x4(qHf[ks], sb + 0 * AT_STG + wr * QSTR + ks * 32 + a_off);
        ldm_x4(qLf[ks], sb + 1 * AT_STG + wr * QSTR + ks * 32 + a_off);
    }
    __syncthreads();

    attn_load_kv(sb, 0, b, hk, 0, kf, vf, tid);
    CP_COMMIT();
    if (1 < ktend) {
        attn_load_kv(sb, 1, b, hk, 1, kf, vf, tid);
        CP_COMMIT();
    }

    float m_i[2] = { -1e30f, -1e30f };
    float l_i[2] = { 0.f, 0.f };
    float o[16][4];
#pragma unroll
    for (int i = 0; i < 16; i++)
#pragma unroll
        for (int j = 0; j < 4; j++) o[i][j] = 0.f;

    for (int kt = 0; kt < ktend; kt++) {
        if (kt + 1 < ktend) { CP_WAIT(1); } else { CP_WAIT(0); }
        __syncthreads();

        const int cst = kt % 3;
        const uint32_t Kb = sb + cst * AT_STG + AT_K;
        const uint32_t Vb = sb + cst * AT_STG + AT_V;

        // ---- S = Q K^T ----
        float s[8][4];
#pragma unroll
        for (int i = 0; i < 8; i++)
#pragma unroll
            for (int j = 0; j < 4; j++) s[i][j] = 0.f;

#pragma unroll
        for (int ks = 0; ks < 8; ks++) {
            const uint32_t kb = ks * 32;
#pragma unroll
            for (int t = 0; t < 4; t++) {
                uint32_t b4[4];
                ldm_x4(b4, Kb + (t * 16) * QSTR + kb + b_off);
                mma_f16(s[2 * t],     qHf[ks], b4[0], b4[1]);
                mma_f16(s[2 * t],     qLf[ks], b4[0], b4[1]);
                mma_f16(s[2 * t + 1], qHf[ks], b4[2], b4[3]);
                mma_f16(s[2 * t + 1], qLf[ks], b4[2], b4[3]);
            }
        }

#pragma unroll
        for (int ni = 0; ni < 8; ni++)
#pragma unroll
            for (int j = 0; j < 4; j++) s[ni][j] *= lscale;

        const int row0 = qt * 64 + wr + g;
        if (causal && (kt * 64 + 63 > qt * 64 + wr)) {
            const int col0 = kt * 64 + 2 * cq;
#pragma unroll
            for (int ni = 0; ni < 8; ni++)
#pragma unroll
                for (int j = 0; j < 4; j++) {
                    int row = row0 + (j >> 1) * 8;
                    int col = col0 + ni * 8 + (j & 1);
                    if (col > row) s[ni][j] = -1e30f;
                }
        }

#pragma unroll
        for (int h = 0; h < 2; h++) {
            float rm = -1e30f;
#pragma unroll
            for (int ni = 0; ni < 8; ni++)
                rm = fmaxf(rm, fmaxf(s[ni][2 * h], s[ni][2 * h + 1]));
            rm = fmaxf(rm, __shfl_xor_sync(0xffffffffu, rm, 1));
            rm = fmaxf(rm, __shfl_xor_sync(0xffffffffu, rm, 2));
            const float mn = fmaxf(m_i[h], rm);
            const float alpha = __expf(m_i[h] - mn);
            m_i[h] = mn;
            float rs = 0.f;
#pragma unroll
            for (int ni = 0; ni < 8; ni++) {
                float e0 = __expf(s[ni][2 * h]     - mn);
                float e1 = __expf(s[ni][2 * h + 1] - mn);
                s[ni][2 * h] = e0; s[ni][2 * h + 1] = e1;
                rs += e0 + e1;
            }
            rs += __shfl_xor_sync(0xffffffffu, rs, 1);
            rs += __shfl_xor_sync(0xffffffffu, rs, 2);
            l_i[h] = l_i[h] * alpha + rs;
#pragma unroll
            for (int np = 0; np < 16; np++) {
                o[np][2 * h]     *= alpha;
                o[np][2 * h + 1] *= alpha;
            }
        }

        // ---- mid-compute load issue: before PV, stage (kt+2)%3 is free ----
        if (kt + 2 < ktend) {
            attn_load_kv(sb, (kt + 2) % 3, b, hk, kt + 2, kf, vf, tid);
            CP_COMMIT();
        }

        // ---- O += P V (fp16, P split 2-term) ----
#pragma unroll
        for (int ks = 0; ks < 4; ks++) {
            uint32_t aPh[4], aPl[4];
#pragma unroll
            for (int q = 0; q < 4; q++) {
                const int ni = 2 * ks + (q >> 1);
                const int j0 = (q & 1) * 2;
                float e0 = s[ni][j0], e1 = s[ni][j0 + 1];
                __half2 hh = __floats2half2_rn(e0, e1);
                aPh[q] = *(uint32_t*)&hh;
                float2 hf = __half22float2(hh);
                __half2 ll = __floats2half2_rn(e0 - hf.x, e1 - hf.y);
                aPl[q] = *(uint32_t*)&ll;
            }
#pragma unroll
            for (int np = 0; np < 8; np++) {
                uint32_t bv[4];
                ldm_x4_t(bv, Vb + (ks * 16) * QSTR + np * 32 + a_off);
                mma_f16(o[2 * np],     aPh, bv[0], bv[1]);
                mma_f16(o[2 * np],     aPl, bv[0], bv[1]);
                mma_f16(o[2 * np + 1], aPh, bv[2], bv[3]);
                mma_f16(o[2 * np + 1], aPl, bv[2], bv[3]);
            }
        }
    }

    const float inv0 = 1.f / l_i[0];
    const float inv1 = 1.f / l_i[1];
    const size_t rowa = (size_t)(b * N_ + qt * 64 + wr + g);
    const int colb = hq * D_ + 2 * cq;
#pragma unroll
    for (int np = 0; np < 16; np++) {
        *(__half2*)(ao + rowa * E_ + colb + np * 8) =
            __floats2half2_rn(o[np][0] * inv0, o[np][1] * inv0);
        *(__half2*)(ao + (rowa + 8) * E_ + colb + np * 8) =
            __floats2half2_rn(o[np][2] * inv1, o[np][3] * inv1);
    }
}

// =================================================================
extern "C" void kernel_launch(void* const* d_in, const int* in_sizes, int n_in,
                              void* d_out, int out_size)
{
    const float* query = (const float*)d_in[0];
    const float* key   = (const float*)d_in[1];
    const float* value = (const float*)d_in[2];
    const float* Wq = (const float*)d_in[3];
    const float* bq = (const float*)d_in[4];
    const float* Wk = (const float*)d_in[5];
    const float* bk = (const float*)d_in[6];
    const float* Wv = (const float*)d_in[7];
    const float* bv = (const float*)d_in[8];
    const float* Wo = (const float*)d_in[9];
    const float* bo = (const float*)d_in[10];
    const int* is_causal = (const int*)d_in[11];
    float* out = (float*)d_out;

    __half *sq, *sk, *sv;
    __half *wqh, *wql, *wkh, *wkl, *wvh, *wvl, *woh, *wol;
    __half *qhp, *qlp, *kfp, *vfp, *afp;
    cudaGetSymbolAddress((void**)&sq, s_q);
    cudaGetSymbolAddress((void**)&sk, s_k);
    cudaGetSymbolAddress((void**)&sv, s_v);
    cudaGetSymbolAddress((void**)&wqh, w_q_h);  cudaGetSymbolAddress((void**)&wql, w_q_l);
    cudaGetSymbolAddress((void**)&wkh, w_k_h);  cudaGetSymbolAddress((void**)&wkl, w_k_l);
    cudaGetSymbolAddress((void**)&wvh, w_v_h);  cudaGetSymbolAddress((void**)&wvl, w_v_l);
    cudaGetSymbolAddress((void**)&woh, w_o_h);  cudaGetSymbolAddress((void**)&wol, w_o_l);
    cudaGetSymbolAddress((void**)&qhp, q_h16);  cudaGetSymbolAddress((void**)&qlp, q_l16);
    cudaGetSymbolAddress((void**)&kfp, k_f16);  cudaGetSymbolAddress((void**)&vfp, v_f16);
    cudaGetSymbolAddress((void**)&afp, a_f16);

    // ---- fused converts (7 segments, one launch) ----
    const int actN4 = (MR_ * E_) / 4;
    const int wqN4  = (E_ * E_) / 4;
    const int wkN4  = (KVE_ * E_) / 4;
    SplitSegs segs;
    segs.x[0] = query; segs.hi[0] = sq;  segs.lo[0] = nullptr;
    segs.x[1] = key;   segs.hi[1] = sk;  segs.lo[1] = nullptr;
    segs.x[2] = value; segs.hi[2] = sv;  segs.lo[2] = nullptr;
    segs.x[3] = Wq;    segs.hi[3] = wqh; segs.lo[3] = wql;
    segs.x[4] = Wk;    segs.hi[4] = wkh; segs.lo[4] = wkl;
    segs.x[5] = Wv;    segs.hi[5] = wvh; segs.lo[5] = wvl;
    segs.x[6] = Wo;    segs.hi[6] = woh; segs.lo[6] = wol;
    int nb = 0;
    const int segBlocks[7] = { actN4/256, actN4/256, actN4/256,
                               wqN4/256, wkN4/256, wkN4/256, wqN4/256 };
    for (int s = 0; s < 7; s++) { nb += segBlocks[s]; segs.blk_end[s] = nb; }
    split_fused<<<nb, 256>>>(segs);

    // ---- fused Q/K/V projection GEMMs ----
    cudaFuncSetAttribute(gemm_qkv, cudaFuncAttributeMaxDynamicSharedMemorySize, GSMEM);
    cudaFuncSetAttribute(gemm_o,   cudaFuncAttributeMaxDynamicSharedMemorySize, GSMEM);
    const int qkvBlocks = (E_ / BN) * (MR_ / BM) + 2 * (KVE_ / BN) * (MR_ / BM); // 768
    gemm_qkv<<<qkvBlocks, 256, GSMEM>>>(
        sq, wqh, wql, bq, qhp, qlp,
        sk, wkh, wkl, bk, kfp,
        sv, wvh, wvl, bv, vfp);

    // ---- HMMA flash attention ----
    cudaFuncSetAttribute(attn_mma, cudaFuncAttributeMaxDynamicSharedMemorySize, AT_SMEM);
    attn_mma<<<dim3(N_ / 64, B_ * HQ_), 128, AT_SMEM>>>(
        qhp, qlp, kfp, vfp, afp, is_causal);

    // ---- O projection (fp32 out) ----
    gemm_o<<<dim3(E_ / BN, MR_ / BM), 256, GSMEM>>>(afp, woh, wol, bo, out);
}

// round 16
// speedup vs baseline: 1.0914x; 1.0084x over previous
#include <cuda_runtime.h>
#include <cuda_bf16.h>
#include <cuda_fp16.h>
#include <cstdint>
#include <math.h>

#define E_    2048
#define HQ_   16
#define HK_   4
#define D_    128
#define KVE_  512
#define B_    2
#define N_    2048
#define MR_   (B_ * N_)   // 4096 rows

// ---------------- scratch (no allocations allowed) ----------------
__device__ __half s_q[(size_t)MR_ * E_];
__device__ __half s_k[(size_t)MR_ * E_];
__device__ __half s_v[(size_t)MR_ * E_];
__device__ __half w_q_h[(size_t)E_ * E_],   w_q_l[(size_t)E_ * E_];
__device__ __half w_k_h[(size_t)KVE_ * E_], w_k_l[(size_t)KVE_ * E_];
__device__ __half w_v_h[(size_t)KVE_ * E_], w_v_l[(size_t)KVE_ * E_];
__device__ __half w_o_h[(size_t)E_ * E_],   w_o_l[(size_t)E_ * E_];
__device__ __half q_h16[(size_t)MR_ * E_], q_l16[(size_t)MR_ * E_];
__device__ __half k_f16[(size_t)MR_ * KVE_];
__device__ __half v_f16[(size_t)MR_ * KVE_];
__device__ __half a_f16[(size_t)MR_ * E_];

// ================= helpers =================
__device__ __forceinline__ uint32_t smem_u32(const void* p) {
    uint32_t a;
    asm("{ .reg .u64 t; cvta.to.shared.u64 t, %1; cvt.u32.u64 %0, t; }" : "=r"(a) : "l"(p));
    return a;
}
__device__ __forceinline__ void cp16(uint32_t saddr, const void* g) {
    asm volatile("cp.async.cg.shared.global [%0], [%1], 16;" :: "r"(saddr), "l"(g));
}
#define CP_COMMIT() asm volatile("cp.async.commit_group;" ::: "memory")
#define CP_WAIT(n)  asm volatile("cp.async.wait_group %0;" :: "n"(n) : "memory")

__device__ __forceinline__ void ldm_x4(uint32_t* r, uint32_t addr) {
    asm volatile("ldmatrix.sync.aligned.m8n8.x4.shared.b16 {%0,%1,%2,%3}, [%4];"
                 : "=r"(r[0]), "=r"(r[1]), "=r"(r[2]), "=r"(r[3]) : "r"(addr));
}
__device__ __forceinline__ void ldm_x4_t(uint32_t* r, uint32_t addr) {
    asm volatile("ldmatrix.sync.aligned.m8n8.x4.trans.shared.b16 {%0,%1,%2,%3}, [%4];"
                 : "=r"(r[0]), "=r"(r[1]), "=r"(r[2]), "=r"(r[3]) : "r"(addr));
}
__device__ __forceinline__ void mma_f16(float* d, const uint32_t* a,
                                        uint32_t b0, uint32_t b1) {
    asm volatile(
        "mma.sync.aligned.m16n8k16.row.col.f32.f16.f16.f32 "
        "{%0,%1,%2,%3}, {%4,%5,%6,%7}, {%8,%9}, {%0,%1,%2,%3};"
        : "+f"(d[0]), "+f"(d[1]), "+f"(d[2]), "+f"(d[3])
        : "r"(a[0]), "r"(a[1]), "r"(a[2]), "r"(a[3]), "r"(b0), "r"(b1));
}
__device__ __forceinline__ void split_store2h(__half* hi, __half* lo,
                                              size_t off, float y0, float y1) {
    __half h0 = __float2half(y0);
    __half h1 = __float2half(y1);
    __half l0 = __float2half(y0 - __half2float(h0));
    __half l1 = __float2half(y1 - __half2float(h1));
    *(__half2*)(hi + off) = __halves2half2(h0, h1);
    *(__half2*)(lo + off) = __halves2half2(l0, l1);
}

// ========== fused convert: fp32 -> fp16 hi(/lo) over 7 segments ==========
struct SplitSegs {
    const float* x[7];
    __half* hi[7];
    __half* lo[7];
    int blk_end[7];
};

__global__ void split_fused(SplitSegs segs)
{
    int bid = blockIdx.x;
    int seg = 0;
    int base = 0;
#pragma unroll
    for (int s = 0; s < 7; s++) {
        if (bid >= segs.blk_end[s]) { seg = s + 1; base = segs.blk_end[s]; }
    }
    int i = (bid - base) * 256 + threadIdx.x;
    float4 v = ((const float4*)segs.x[seg])[i];
    __half h0 = __float2half(v.x);
    __half h1 = __float2half(v.y);
    __half h2 = __float2half(v.z);
    __half h3 = __float2half(v.w);
    __half* hi = segs.hi[seg];
    ((__half2*)hi)[i * 2]     = __halves2half2(h0, h1);
    ((__half2*)hi)[i * 2 + 1] = __halves2half2(h2, h3);
    __half* lo = segs.lo[seg];
    if (lo) {
        __half l0 = __float2half(v.x - __half2float(h0));
        __half l1 = __float2half(v.y - __half2float(h1));
        __half l2 = __float2half(v.z - __half2float(h2));
        __half l3 = __float2half(v.w - __half2float(h3));
        ((__half2*)lo)[i * 2]     = __halves2half2(l0, l1);
        ((__half2*)lo)[i * 2 + 1] = __halves2half2(l2, l3);
    }
}

// ====== HMMA NT GEMM core (fp16, B(weight)-split 2-term, 3-stage BK=32) ======
// R15 config: mid-compute cp.async issue (proven 67.2% tensor).
#define BM 128
#define BN 128
#define BK 32
#define LDSB 80
#define TILE_B (128 * LDSB)      // 10240
#define STAGE_B (3 * TILE_B)     // A, Bh, Bl = 30720
#define GSMEM (3 * STAGE_B)      // 92160 (3 stages)

__device__ __forceinline__ void load_chunk(uint32_t sb, int stage,
    const __half* __restrict__ Aa, const __half* __restrict__ Bh,
    const __half* __restrict__ Bl, int K, int tid)
{
    const __half* srcs[3] = { Aa, Bh, Bl };
    uint32_t base = sb + stage * STAGE_B;
#pragma unroll
    for (int t = 0; t < 3; t++) {
#pragma unroll
        for (int it = 0; it < 2; it++) {
            int idx = tid + it * 256;
            int r = idx >> 2;
            int c = idx & 3;
            cp16(base + t * TILE_B + r * LDSB + c * 16,
                 srcs[t] + (size_t)r * K + c * 8);
        }
    }
}

__device__ __forceinline__ void gemm_mainloop(
    uint32_t sb, const __half* pA, const __half* pBh, const __half* pBl,
    int K, int tid, int lane, int wm, int wn, float acc[4][4][4])
{
    const uint32_t a_off = (uint32_t)((lane & 15) * LDSB + (lane >> 4) * 16);
    const uint32_t b_off = (uint32_t)(((lane & 7) + (lane >> 4) * 8) * LDSB
                                      + ((lane >> 3) & 1) * 16);
    const int nch = K >> 5;

    load_chunk(sb, 0, pA, pBh, pBl, K, tid);
    CP_COMMIT();
    load_chunk(sb, 1, pA + BK, pBh + BK, pBl + BK, K, tid);
    CP_COMMIT();

    int cst = 0;
    int lst = 2;
    for (int c = 0; c < nch; c++) {
        if (c + 1 < nch) { CP_WAIT(1); } else { CP_WAIT(0); }
        __syncthreads();

        const uint32_t stb = sb + cst * STAGE_B;
        const uint32_t A_b  = stb + 0 * TILE_B;
        const uint32_t Bh_b = stb + 1 * TILE_B;
        const uint32_t Bl_b = stb + 2 * TILE_B;

#pragma unroll
        for (int ks = 0; ks < 2; ks++) {
            const uint32_t kbyte = ks * 32;
            uint32_t aS[4][4], bH[2][4], bL[2][4];
#pragma unroll
            for (int mi = 0; mi < 4; mi++)
                ldm_x4(aS[mi], A_b + (wm * 64 + mi * 16) * LDSB + kbyte + a_off);
#pragma unroll
            for (int nb = 0; nb < 2; nb++) {
                ldm_x4(bH[nb], Bh_b + (wn * 32 + nb * 16) * LDSB + kbyte + b_off);
                ldm_x4(bL[nb], Bl_b + (wn * 32 + nb * 16) * LDSB + kbyte + b_off);
            }
#pragma unroll
            for (int mi = 0; mi < 4; mi++)
#pragma unroll
                for (int ni = 0; ni < 4; ni++)
                    mma_f16(acc[mi][ni], aS[mi], bH[ni >> 1][(ni & 1) * 2],
                                                  bH[ni >> 1][(ni & 1) * 2 + 1]);
#pragma unroll
            for (int mi = 0; mi < 4; mi++)
#pragma unroll
                for (int ni = 0; ni < 4; ni++)
                    mma_f16(acc[mi][ni], aS[mi], bL[ni >> 1][(ni & 1) * 2],
                                                  bL[ni >> 1][(ni & 1) * 2 + 1]);

            // mid-compute load issue: after ks=0's MMA stream is in flight
            if (ks == 0 && c + 2 < nch) {
                const size_t kb = (size_t)(c + 2) * BK;
                load_chunk(sb, lst, pA + kb, pBh + kb, pBl + kb, K, tid);
                CP_COMMIT();
            }
        }
        cst = (cst == 2) ? 0 : cst + 1;
        lst = (lst == 2) ? 0 : lst + 1;
    }
}

// ---- fused Q/K/V projection GEMM (one launch) ----
__global__ void __launch_bounds__(256, 2) gemm_qkv(
    const __half* __restrict__ sq, const __half* __restrict__ wqh,
    const __half* __restrict__ wql, const float* __restrict__ bq,
    __half* __restrict__ qhp, __half* __restrict__ qlp,
    const __half* __restrict__ sk, const __half* __restrict__ wkh,
    const __half* __restrict__ wkl, const float* __restrict__ bk,
    __half* __restrict__ kfp,
    const __half* __restrict__ sv, const __half* __restrict__ wvh,
    const __half* __restrict__ wvl, const float* __restrict__ bv,
    __half* __restrict__ vfp)
{
    extern __shared__ char smem[];
    const uint32_t sb = smem_u32(smem);
    const int tid = threadIdx.x;
    const int lane = tid & 31;
    const int wid = tid >> 5;
    const int wm = wid & 1;
    const int wn = wid >> 1;

    const int bid = blockIdx.x;
    const int seg = (bid < 512) ? 0 : (bid < 640 ? 1 : 2);
    const int local = bid - (seg == 0 ? 0 : (seg == 1 ? 512 : 640));
    const int tilesX = (seg == 0) ? (E_ / BN) : (KVE_ / BN);
    const int m0 = (local / tilesX) * BM;
    const int n0 = (local % tilesX) * BN;

    const __half* Aa = (seg == 0) ? sq : (seg == 1 ? sk : sv);
    const __half* Bh = (seg == 0) ? wqh : (seg == 1 ? wkh : wvh);
    const __half* Bl = (seg == 0) ? wql : (seg == 1 ? wkl : wvl);
    const float* bias = (seg == 0) ? bq : (seg == 1 ? bk : bv);
    const int Nn = (seg == 0) ? E_ : KVE_;

    float acc[4][4][4];
#pragma unroll
    for (int i = 0; i < 4; i++)
#pragma unroll
        for (int j = 0; j < 4; j++)
#pragma unroll
            for (int q = 0; q < 4; q++) acc[i][j][q] = 0.f;

    gemm_mainloop(sb, Aa + (size_t)m0 * E_, Bh + (size_t)n0 * E_,
                  Bl + (size_t)n0 * E_, E_, tid, lane, wm, wn, acc);

    const int g = lane >> 2;
    const int cq = lane & 3;
#pragma unroll
    for (int mi = 0; mi < 4; mi++) {
#pragma unroll
        for (int ni = 0; ni < 4; ni++) {
            const int col = n0 + wn * 32 + ni * 8 + cq * 2;
            const float b0 = bias[col];
            const float b1 = bias[col + 1];
#pragma unroll
            for (int h = 0; h < 2; h++) {
                const int row = m0 + wm * 64 + mi * 16 + g + h * 8;
                const float y0 = acc[mi][ni][h * 2 + 0] + b0;
                const float y1 = acc[mi][ni][h * 2 + 1] + b1;
                const size_t off = (size_t)row * Nn + col;
                if (seg == 0)      split_store2h(qhp, qlp, off, y0, y1);
                else if (seg == 1) *(__half2*)(kfp + off) = __floats2half2_rn(y0, y1);
                else               *(__half2*)(vfp + off) = __floats2half2_rn(y0, y1);
            }
        }
    }
}

// ---- O projection GEMM (fp32 out) ----
__global__ void __launch_bounds__(256, 2) gemm_o(
    const __half* __restrict__ Aa, const __half* __restrict__ Bh,
    const __half* __restrict__ Bl,
    const float* __restrict__ bias, float* __restrict__ C)
{
    extern __shared__ char smem[];
    const uint32_t sb = smem_u32(smem);
    const int tid = threadIdx.x;
    const int lane = tid & 31;
    const int wid = tid >> 5;
    const int wm = wid & 1;
    const int wn = wid >> 1;
    const int m0 = blockIdx.y * BM;
    const int n0 = blockIdx.x * BN;

    float acc[4][4][4];
#pragma unroll
    for (int i = 0; i < 4; i++)
#pragma unroll
        for (int j = 0; j < 4; j++)
#pragma unroll
            for (int q = 0; q < 4; q++) acc[i][j][q] = 0.f;

    gemm_mainloop(sb, Aa + (size_t)m0 * E_, Bh + (size_t)n0 * E_,
                  Bl + (size_t)n0 * E_, E_, tid, lane, wm, wn, acc);

    const int g = lane >> 2;
    const int cq = lane & 3;
#pragma unroll
    for (int mi = 0; mi < 4; mi++) {
#pragma unroll
        for (int ni = 0; ni < 4; ni++) {
            const int col = n0 + wn * 32 + ni * 8 + cq * 2;
            const float b0 = bias[col];
            const float b1 = bias[col + 1];
#pragma unroll
            for (int h = 0; h < 2; h++) {
                const int row = m0 + wm * 64 + mi * 16 + g + h * 8;
                float2 v;
                v.x = acc[mi][ni][h * 2 + 0] + b0;
                v.y = acc[mi][ni][h * 2 + 1] + b1;
                *(float2*)(C + (size_t)row * E_ + col) = v;
            }
        }
    }
}

// =================================================================
// HMMA flash attention: 64 q-rows/CTA, 128 threads, Q in regs,
// 3-stage KV, mid-compute load issue, 2 CTAs/SM.
// R16: exp2-domain softmax (scale folded), ballot-guarded o-rescale.
// =================================================================
#define QSTR 272
#define AT_STG  (2 * 64 * QSTR)        // 34816 (K, V)
#define AT_K    0
#define AT_V    (64 * QSTR)
#define AT_SMEM (3 * AT_STG)           // 104448 -> 2 CTAs/SM

__device__ __forceinline__ void attn_load_kv(uint32_t sb, int stage, int b, int hk,
                                             int kt, const __half* kf,
                                             const __half* vf, int tid)
{
    const uint32_t base = sb + stage * AT_STG;
    const size_t rowg = (size_t)(b * N_ + kt * 64);
#pragma unroll
    for (int it = 0; it < 16; it++) {
        int idx = tid + it * 128;              // 0..2047
        int buf = idx >> 10;                   // 0: K, 1: V
        int r = (idx & 1023) >> 4;             // 0..63
        int c = idx & 15;
        uint32_t dst = base + (buf ? AT_V : AT_K) + r * QSTR + c * 16;
        const __half* src = buf ? vf : kf;
        cp16(dst, src + (rowg + r) * KVE_ + hk * D_ + c * 8);
    }
}

__global__ void __launch_bounds__(128, 2) attn_mma(
    const __half* __restrict__ qh, const __half* __restrict__ ql,
    const __half* __restrict__ kf, const __half* __restrict__ vf,
    __half* __restrict__ ao,
    const int* __restrict__ causal_p)
{
    extern __shared__ char smem[];
    const uint32_t sb = smem_u32(smem);
    const int tid = threadIdx.x;
    const int lane = tid & 31;
    const int wid = tid >> 5;
    const int qt = (int)(gridDim.x - 1 - blockIdx.x);  // heavy tiles first
    const int bh = blockIdx.y;
    const int b  = bh >> 4;
    const int hq = bh & 15;
    const int hk = hq >> 2;
    const int wr = wid * 16;
    const int g = lane >> 2;
    const int cq = lane & 3;
    const bool causal = (causal_p[0] != 0);
    // log2(e) / sqrt(128): exp(x/sqrt(D)) == exp2(x * l2s)
    const float l2s = 0.12751875732437f;

    const uint32_t a_off = (uint32_t)((lane & 15) * QSTR + (lane >> 4) * 16);
    const uint32_t b_off = (uint32_t)(((lane & 7) + (lane >> 4) * 8) * QSTR
                                      + ((lane >> 3) & 1) * 16);

    const int ktend = causal ? (qt + 1) : (N_ / 64);

    // ---- prologue A: stage Q tile (hi+lo) through stages 0/1 smem ----
    {
        const size_t rowg = (size_t)(b * N_ + qt * 64);
#pragma unroll
        for (int it = 0; it < 16; it++) {
            int idx = tid + it * 128;
            int buf = idx >> 10;
            int r = (idx & 1023) >> 4;
            int c = idx & 15;
            uint32_t dst = sb + buf * AT_STG + r * QSTR + c * 16;
            const __half* src = buf ? ql : qh;
            cp16(dst, src + (rowg + r) * E_ + hq * D_ + c * 8);
        }
    }
    CP_COMMIT();
    CP_WAIT(0);
    __syncthreads();

    uint32_t qHf[8][4], qLf[8][4];
#pragma unroll
    for (int ks = 0; ks < 8; ks++) {
        ldm_x4(qHf[ks], sb + 0 * AT_STG + wr * QSTR + ks * 32 + a_off);
        ldm_x4(qLf[ks], sb + 1 * AT_STG + wr * QSTR + ks * 32 + a_off);
    }
    __syncthreads();

    attn_load_kv(sb, 0, b, hk, 0, kf, vf, tid);
    CP_COMMIT();
    if (1 < ktend) {
        attn_load_kv(sb, 1, b, hk, 1, kf, vf, tid);
        CP_COMMIT();
    }

    float m_i[2] = { -1e30f, -1e30f };   // raw-logit domain
    float l_i[2] = { 0.f, 0.f };
    float o[16][4];
#pragma unroll
    for (int i = 0; i < 16; i++)
#pragma unroll
        for (int j = 0; j < 4; j++) o[i][j] = 0.f;

    for (int kt = 0; kt < ktend; kt++) {
        if (kt + 1 < ktend) { CP_WAIT(1); } else { CP_WAIT(0); }
        __syncthreads();

        const int cst = kt % 3;
        const uint32_t Kb = sb + cst * AT_STG + AT_K;
        const uint32_t Vb = sb + cst * AT_STG + AT_V;

        // ---- S = Q K^T (raw logits) ----
        float s[8][4];
#pragma unroll
        for (int i = 0; i < 8; i++)
#pragma unroll
            for (int j = 0; j < 4; j++) s[i][j] = 0.f;

#pragma unroll
        for (int ks = 0; ks < 8; ks++) {
            const uint32_t kb = ks * 32;
#pragma unroll
            for (int t = 0; t < 4; t++) {
                uint32_t b4[4];
                ldm_x4(b4, Kb + (t * 16) * QSTR + kb + b_off);
                mma_f16(s[2 * t],     qHf[ks], b4[0], b4[1]);
                mma_f16(s[2 * t],     qLf[ks], b4[0], b4[1]);
                mma_f16(s[2 * t + 1], qHf[ks], b4[2], b4[3]);
                mma_f16(s[2 * t + 1], qLf[ks], b4[2], b4[3]);
            }
        }

        // ---- causal mask on raw logits ----
        const int row0 = qt * 64 + wr + g;
        if (causal && (kt * 64 + 63 > qt * 64 + wr)) {
            const int col0 = kt * 64 + 2 * cq;
#pragma unroll
            for (int ni = 0; ni < 8; ni++)
#pragma unroll
                for (int j = 0; j < 4; j++) {
                    int row = row0 + (j >> 1) * 8;
                    int col = col0 + ni * 8 + (j & 1);
                    if (col > row) s[ni][j] = -1e30f;
                }
        }

        // ---- online softmax in exp2 domain (scale folded into l2s) ----
#pragma unroll
        for (int h = 0; h < 2; h++) {
            float rm = -1e30f;
#pragma unroll
            for (int ni = 0; ni < 8; ni++)
                rm = fmaxf(rm, fmaxf(s[ni][2 * h], s[ni][2 * h + 1]));
            rm = fmaxf(rm, __shfl_xor_sync(0xffffffffu, rm, 1));
            rm = fmaxf(rm, __shfl_xor_sync(0xffffffffu, rm, 2));
            const float mold = m_i[h];
            const float mn = fmaxf(mold, rm);
            m_i[h] = mn;
            float rs = 0.f;
#pragma unroll
            for (int ni = 0; ni < 8; ni++) {
                float e0 = exp2f((s[ni][2 * h]     - mn) * l2s);
                float e1 = exp2f((s[ni][2 * h + 1] - mn) * l2s);
                s[ni][2 * h] = e0; s[ni][2 * h + 1] = e1;
                rs += e0 + e1;
            }
            rs += __shfl_xor_sync(0xffffffffu, rs, 1);
            rs += __shfl_xor_sync(0xffffffffu, rs, 2);
            const float alpha = exp2f((mold - mn) * l2s);
            l_i[h] = l_i[h] * alpha + rs;
            // skip the o-rescale entirely when no lane's max moved
            if (__ballot_sync(0xffffffffu, mold != mn)) {
#pragma unroll
                for (int np = 0; np < 16; np++) {
                    o[np][2 * h]     *= alpha;
                    o[np][2 * h + 1] *= alpha;
                }
            }
        }

        // ---- mid-compute load issue: before PV, stage (kt+2)%3 is free ----
        if (kt + 2 < ktend) {
            attn_load_kv(sb, (kt + 2) % 3, b, hk, kt + 2, kf, vf, tid);
            CP_COMMIT();
        }

        // ---- O += P V (fp16, P split 2-term) ----
#pragma unroll
        for (int ks = 0; ks < 4; ks++) {
            uint32_t aPh[4], aPl[4];
#pragma unroll
            for (int q = 0; q < 4; q++) {
                const int ni = 2 * ks + (q >> 1);
                const int j0 = (q & 1) * 2;
                float e0 = s[ni][j0], e1 = s[ni][j0 + 1];
                __half2 hh = __floats2half2_rn(e0, e1);
                aPh[q] = *(uint32_t*)&hh;
                float2 hf = __half22float2(hh);
                __half2 ll = __floats2half2_rn(e0 - hf.x, e1 - hf.y);
                aPl[q] = *(uint32_t*)&ll;
            }
#pragma unroll
            for (int np = 0; np < 8; np++) {
                uint32_t bv[4];
                ldm_x4_t(bv, Vb + (ks * 16) * QSTR + np * 32 + a_off);
                mma_f16(o[2 * np],     aPh, bv[0], bv[1]);
                mma_f16(o[2 * np],     aPl, bv[0], bv[1]);
                mma_f16(o[2 * np + 1], aPh, bv[2], bv[3]);
                mma_f16(o[2 * np + 1], aPl, bv[2], bv[3]);
            }
        }
    }

    const float inv0 = 1.f / l_i[0];
    const float inv1 = 1.f / l_i[1];
    const size_t rowa = (size_t)(b * N_ + qt * 64 + wr + g);
    const int colb = hq * D_ + 2 * cq;
#pragma unroll
    for (int np = 0; np < 16; np++) {
        *(__half2*)(ao + rowa * E_ + colb + np * 8) =
            __floats2half2_rn(o[np][0] * inv0, o[np][1] * inv0);
        *(__half2*)(ao + (rowa + 8) * E_ + colb + np * 8) =
            __floats2half2_rn(o[np][2] * inv1, o[np][3] * inv1);
    }
}

// =================================================================
extern "C" void kernel_launch(void* const* d_in, const int* in_sizes, int n_in,
                              void* d_out, int out_size)
{
    const float* query = (const float*)d_in[0];
    const float* key   = (const float*)d_in[1];
    const float* value = (const float*)d_in[2];
    const float* Wq = (const float*)d_in[3];
    const float* bq = (const float*)d_in[4];
    const float* Wk = (const float*)d_in[5];
    const float* bk = (const float*)d_in[6];
    const float* Wv = (const float*)d_in[7];
    const float* bv = (const float*)d_in[8];
    const float* Wo = (const float*)d_in[9];
    const float* bo = (const float*)d_in[10];
    const int* is_causal = (const int*)d_in[11];
    float* out = (float*)d_out;

    __half *sq, *sk, *sv;
    __half *wqh, *wql, *wkh, *wkl, *wvh, *wvl, *woh, *wol;
    __half *qhp, *qlp, *kfp, *vfp, *afp;
    cudaGetSymbolAddress((void**)&sq, s_q);
    cudaGetSymbolAddress((void**)&sk, s_k);
    cudaGetSymbolAddress((void**)&sv, s_v);
    cudaGetSymbolAddress((void**)&wqh, w_q_h);  cudaGetSymbolAddress((void**)&wql, w_q_l);
    cudaGetSymbolAddress((void**)&wkh, w_k_h);  cudaGetSymbolAddress((void**)&wkl, w_k_l);
    cudaGetSymbolAddress((void**)&wvh, w_v_h);  cudaGetSymbolAddress((void**)&wvl, w_v_l);
    cudaGetSymbolAddress((void**)&woh, w_o_h);  cudaGetSymbolAddress((void**)&wol, w_o_l);
    cudaGetSymbolAddress((void**)&qhp, q_h16);  cudaGetSymbolAddress((void**)&qlp, q_l16);
    cudaGetSymbolAddress((void**)&kfp, k_f16);  cudaGetSymbolAddress((void**)&vfp, v_f16);
    cudaGetSymbolAddress((void**)&afp, a_f16);

    // ---- fused converts (7 segments, one launch) ----
    const int actN4 = (MR_ * E_) / 4;
    const int wqN4  = (E_ * E_) / 4;
    const int wkN4  = (KVE_ * E_) / 4;
    SplitSegs segs;
    segs.x[0] = query; segs.hi[0] = sq;  segs.lo[0] = nullptr;
    segs.x[1] = key;   segs.hi[1] = sk;  segs.lo[1] = nullptr;
    segs.x[2] = value; segs.hi[2] = sv;  segs.lo[2] = nullptr;
    segs.x[3] = Wq;    segs.hi[3] = wqh; segs.lo[3] = wql;
    segs.x[4] = Wk;    segs.hi[4] = wkh; segs.lo[4] = wkl;
    segs.x[5] = Wv;    segs.hi[5] = wvh; segs.lo[5] = wvl;
    segs.x[6] = Wo;    segs.hi[6] = woh; segs.lo[6] = wol;
    int nb = 0;
    const int segBlocks[7] = { actN4/256, actN4/256, actN4/256,
                               wqN4/256, wkN4/256, wkN4/256, wqN4/256 };
    for (int s = 0; s < 7; s++) { nb += segBlocks[s]; segs.blk_end[s] = nb; }
    split_fused<<<nb, 256>>>(segs);

    // ---- fused Q/K/V projection GEMMs ----
    cudaFuncSetAttribute(gemm_qkv, cudaFuncAttributeMaxDynamicSharedMemorySize, GSMEM);
    cudaFuncSetAttribute(gemm_o,   cudaFuncAttributeMaxDynamicSharedMemorySize, GSMEM);
    const int qkvBlocks = (E_ / BN) * (MR_ / BM) + 2 * (KVE_ / BN) * (MR_ / BM); // 768
    gemm_qkv<<<qkvBlocks, 256, GSMEM>>>(
        sq, wqh, wql, bq, qhp, qlp,
        sk, wkh, wkl, bk, kfp,
        sv, wvh, wvl, bv, vfp);

    // ---- HMMA flash attention ----
    cudaFuncSetAttribute(attn_mma, cudaFuncAttributeMaxDynamicSharedMemorySize, AT_SMEM);
    attn_mma<<<dim3(N_ / 64, B_ * HQ_), 128, AT_SMEM>>>(
        qhp, qlp, kfp, vfp, afp, is_causal);

    // ---- O projection (fp32 out) ----
    gemm_o<<<dim3(E_ / BN, MR_ / BM), 256, GSMEM>>>(afp, woh, wol, bo, out);
}

// round 17
// speedup vs baseline: 1.1707x; 1.0726x over previous
#include <cuda_runtime.h>
#include <cuda_bf16.h>
#include <cuda_fp16.h>
#include <cstdint>
#include <math.h>

#define E_    2048
#define HQ_   16
#define HK_   4
#define D_    128
#define KVE_  512
#define B_    2
#define N_    2048
#define MR_   (B_ * N_)   // 4096 rows

// ---------------- scratch (no allocations allowed) ----------------
__device__ __half s_q[(size_t)MR_ * E_];
__device__ __half s_k[(size_t)MR_ * E_];
__device__ __half s_v[(size_t)MR_ * E_];
__device__ __half w_q_h[(size_t)E_ * E_],   w_q_l[(size_t)E_ * E_];
__device__ __half w_k_h[(size_t)KVE_ * E_];               // single fp16 now
__device__ __half w_v_h[(size_t)KVE_ * E_];               // single fp16 now
__device__ __half w_o_h[(size_t)E_ * E_],   w_o_l[(size_t)E_ * E_];
__device__ __half q_h16[(size_t)MR_ * E_], q_l16[(size_t)MR_ * E_];
__device__ __half k_f16[(size_t)MR_ * KVE_];
__device__ __half v_f16[(size_t)MR_ * KVE_];
__device__ __half a_f16[(size_t)MR_ * E_];

// ================= helpers =================
__device__ __forceinline__ uint32_t smem_u32(const void* p) {
    uint32_t a;
    asm("{ .reg .u64 t; cvta.to.shared.u64 t, %1; cvt.u32.u64 %0, t; }" : "=r"(a) : "l"(p));
    return a;
}
__device__ __forceinline__ void cp16(uint32_t saddr, const void* g) {
    asm volatile("cp.async.cg.shared.global [%0], [%1], 16;" :: "r"(saddr), "l"(g));
}
#define CP_COMMIT() asm volatile("cp.async.commit_group;" ::: "memory")
#define CP_WAIT(n)  asm volatile("cp.async.wait_group %0;" :: "n"(n) : "memory")

__device__ __forceinline__ void ldm_x4(uint32_t* r, uint32_t addr) {
    asm volatile("ldmatrix.sync.aligned.m8n8.x4.shared.b16 {%0,%1,%2,%3}, [%4];"
                 : "=r"(r[0]), "=r"(r[1]), "=r"(r[2]), "=r"(r[3]) : "r"(addr));
}
__device__ __forceinline__ void ldm_x4_t(uint32_t* r, uint32_t addr) {
    asm volatile("ldmatrix.sync.aligned.m8n8.x4.trans.shared.b16 {%0,%1,%2,%3}, [%4];"
                 : "=r"(r[0]), "=r"(r[1]), "=r"(r[2]), "=r"(r[3]) : "r"(addr));
}
__device__ __forceinline__ void mma_f16(float* d, const uint32_t* a,
                                        uint32_t b0, uint32_t b1) {
    asm volatile(
        "mma.sync.aligned.m16n8k16.row.col.f32.f16.f16.f32 "
        "{%0,%1,%2,%3}, {%4,%5,%6,%7}, {%8,%9}, {%0,%1,%2,%3};"
        : "+f"(d[0]), "+f"(d[1]), "+f"(d[2]), "+f"(d[3])
        : "r"(a[0]), "r"(a[1]), "r"(a[2]), "r"(a[3]), "r"(b0), "r"(b1));
}
__device__ __forceinline__ void split_store2h(__half* hi, __half* lo,
                                              size_t off, float y0, float y1) {
    __half h0 = __float2half(y0);
    __half h1 = __float2half(y1);
    __half l0 = __float2half(y0 - __half2float(h0));
    __half l1 = __float2half(y1 - __half2float(h1));
    *(__half2*)(hi + off) = __halves2half2(h0, h1);
    *(__half2*)(lo + off) = __halves2half2(l0, l1);
}

// ========== fused convert: fp32 -> fp16 hi(/lo) over 7 segments ==========
struct SplitSegs {
    const float* x[7];
    __half* hi[7];
    __half* lo[7];
    int blk_end[7];
};

__global__ void split_fused(SplitSegs segs)
{
    int bid = blockIdx.x;
    int seg = 0;
    int base = 0;
#pragma unroll
    for (int s = 0; s < 7; s++) {
        if (bid >= segs.blk_end[s]) { seg = s + 1; base = segs.blk_end[s]; }
    }
    int i = (bid - base) * 256 + threadIdx.x;
    float4 v = ((const float4*)segs.x[seg])[i];
    __half h0 = __float2half(v.x);
    __half h1 = __float2half(v.y);
    __half h2 = __float2half(v.z);
    __half h3 = __float2half(v.w);
    __half* hi = segs.hi[seg];
    ((__half2*)hi)[i * 2]     = __halves2half2(h0, h1);
    ((__half2*)hi)[i * 2 + 1] = __halves2half2(h2, h3);
    __half* lo = segs.lo[seg];
    if (lo) {
        __half l0 = __float2half(v.x - __half2float(h0));
        __half l1 = __float2half(v.y - __half2float(h1));
        __half l2 = __float2half(v.z - __half2float(h2));
        __half l3 = __float2half(v.w - __half2float(h3));
        ((__half2*)lo)[i * 2]     = __halves2half2(l0, l1);
        ((__half2*)lo)[i * 2 + 1] = __halves2half2(l2, l3);
    }
}

// ====== HMMA NT GEMM core (fp16, templated B-split, 3-stage BK=32) ======
// R15/R16 config: mid-compute cp.async issue.
#define BM 128
#define BN 128
#define BK 32
#define LDSB 80
#define TILE_B (128 * LDSB)      // 10240
#define STAGE_B (3 * TILE_B)     // A, Bh, Bl = 30720 (Bl slot unused if !SPLITB)
#define GSMEM (3 * STAGE_B)      // 92160 (3 stages)

template <bool SPLITB>
__device__ __forceinline__ void load_chunk(uint32_t sb, int stage,
    const __half* __restrict__ Aa, const __half* __restrict__ Bh,
    const __half* __restrict__ Bl, int K, int tid)
{
    uint32_t base = sb + stage * STAGE_B;
    const int nt = SPLITB ? 3 : 2;
    const __half* srcs[3] = { Aa, Bh, Bl };
#pragma unroll
    for (int t = 0; t < nt; t++) {
#pragma unroll
        for (int it = 0; it < 2; it++) {
            int idx = tid + it * 256;
            int r = idx >> 2;
            int c = idx & 3;
            cp16(base + t * TILE_B + r * LDSB + c * 16,
                 srcs[t] + (size_t)r * K + c * 8);
        }
    }
}

template <bool SPLITB>
__device__ __forceinline__ void gemm_mainloop(
    uint32_t sb, const __half* pA, const __half* pBh, const __half* pBl,
    int K, int tid, int lane, int wm, int wn, float acc[4][4][4])
{
    const uint32_t a_off = (uint32_t)((lane & 15) * LDSB + (lane >> 4) * 16);
    const uint32_t b_off = (uint32_t)(((lane & 7) + (lane >> 4) * 8) * LDSB
                                      + ((lane >> 3) & 1) * 16);
    const int nch = K >> 5;

    load_chunk<SPLITB>(sb, 0, pA, pBh, pBl, K, tid);
    CP_COMMIT();
    load_chunk<SPLITB>(sb, 1, pA + BK, pBh + BK, pBl + BK, K, tid);
    CP_COMMIT();

    int cst = 0;
    int lst = 2;
    for (int c = 0; c < nch; c++) {
        if (c + 1 < nch) { CP_WAIT(1); } else { CP_WAIT(0); }
        __syncthreads();

        const uint32_t stb = sb + cst * STAGE_B;
        const uint32_t A_b  = stb + 0 * TILE_B;
        const uint32_t Bh_b = stb + 1 * TILE_B;
        const uint32_t Bl_b = stb + 2 * TILE_B;

#pragma unroll
        for (int ks = 0; ks < 2; ks++) {
            const uint32_t kbyte = ks * 32;
            uint32_t aS[4][4], bH[2][4], bL[2][4];
#pragma unroll
            for (int mi = 0; mi < 4; mi++)
                ldm_x4(aS[mi], A_b + (wm * 64 + mi * 16) * LDSB + kbyte + a_off);
#pragma unroll
            for (int nb = 0; nb < 2; nb++) {
                ldm_x4(bH[nb], Bh_b + (wn * 32 + nb * 16) * LDSB + kbyte + b_off);
                if (SPLITB)
                    ldm_x4(bL[nb], Bl_b + (wn * 32 + nb * 16) * LDSB + kbyte + b_off);
            }
#pragma unroll
            for (int mi = 0; mi < 4; mi++)
#pragma unroll
                for (int ni = 0; ni < 4; ni++)
                    mma_f16(acc[mi][ni], aS[mi], bH[ni >> 1][(ni & 1) * 2],
                                                  bH[ni >> 1][(ni & 1) * 2 + 1]);
            if (SPLITB) {
#pragma unroll
                for (int mi = 0; mi < 4; mi++)
#pragma unroll
                    for (int ni = 0; ni < 4; ni++)
                        mma_f16(acc[mi][ni], aS[mi], bL[ni >> 1][(ni & 1) * 2],
                                                      bL[ni >> 1][(ni & 1) * 2 + 1]);
            }

            // mid-compute load issue: after ks=0's MMA stream is in flight
            if (ks == 0 && c + 2 < nch) {
                const size_t kb = (size_t)(c + 2) * BK;
                load_chunk<SPLITB>(sb, lst, pA + kb, pBh + kb, pBl + kb, K, tid);
                CP_COMMIT();
            }
        }
        cst = (cst == 2) ? 0 : cst + 1;
        lst = (lst == 2) ? 0 : lst + 1;
    }
}

// ---- fused Q/K/V projection GEMM (one launch) ----
// blocks [0,512): Q (split W), [512,640): K (single W), [640,768): V (single W)
__global__ void __launch_bounds__(256, 2) gemm_qkv(
    const __half* __restrict__ sq, const __half* __restrict__ wqh,
    const __half* __restrict__ wql, const float* __restrict__ bq,
    __half* __restrict__ qhp, __half* __restrict__ qlp,
    const __half* __restrict__ sk, const __half* __restrict__ wkh,
    const float* __restrict__ bk, __half* __restrict__ kfp,
    const __half* __restrict__ sv, const __half* __restrict__ wvh,
    const float* __restrict__ bv, __half* __restrict__ vfp)
{
    extern __shared__ char smem[];
    const uint32_t sb = smem_u32(smem);
    const int tid = threadIdx.x;
    const int lane = tid & 31;
    const int wid = tid >> 5;
    const int wm = wid & 1;
    const int wn = wid >> 1;

    const int bid = blockIdx.x;
    const int seg = (bid < 512) ? 0 : (bid < 640 ? 1 : 2);
    const int local = bid - (seg == 0 ? 0 : (seg == 1 ? 512 : 640));
    const int tilesX = (seg == 0) ? (E_ / BN) : (KVE_ / BN);
    const int m0 = (local / tilesX) * BM;
    const int n0 = (local % tilesX) * BN;

    const __half* Aa = (seg == 0) ? sq : (seg == 1 ? sk : sv);
    const __half* Bh = (seg == 0) ? wqh : (seg == 1 ? wkh : wvh);
    const float* bias = (seg == 0) ? bq : (seg == 1 ? bk : bv);
    const int Nn = (seg == 0) ? E_ : KVE_;

    float acc[4][4][4];
#pragma unroll
    for (int i = 0; i < 4; i++)
#pragma unroll
        for (int j = 0; j < 4; j++)
#pragma unroll
            for (int q = 0; q < 4; q++) acc[i][j][q] = 0.f;

    if (seg == 0)
        gemm_mainloop<true>(sb, Aa + (size_t)m0 * E_, Bh + (size_t)n0 * E_,
                            wql + (size_t)n0 * E_, E_, tid, lane, wm, wn, acc);
    else
        gemm_mainloop<false>(sb, Aa + (size_t)m0 * E_, Bh + (size_t)n0 * E_,
                             nullptr, E_, tid, lane, wm, wn, acc);

    const int g = lane >> 2;
    const int cq = lane & 3;
#pragma unroll
    for (int mi = 0; mi < 4; mi++) {
#pragma unroll
        for (int ni = 0; ni < 4; ni++) {
            const int col = n0 + wn * 32 + ni * 8 + cq * 2;
            const float b0 = bias[col];
            const float b1 = bias[col + 1];
#pragma unroll
            for (int h = 0; h < 2; h++) {
                const int row = m0 + wm * 64 + mi * 16 + g + h * 8;
                const float y0 = acc[mi][ni][h * 2 + 0] + b0;
                const float y1 = acc[mi][ni][h * 2 + 1] + b1;
                const size_t off = (size_t)row * Nn + col;
                if (seg == 0)      split_store2h(qhp, qlp, off, y0, y1);
                else if (seg == 1) *(__half2*)(kfp + off) = __floats2half2_rn(y0, y1);
                else               *(__half2*)(vfp + off) = __floats2half2_rn(y0, y1);
            }
        }
    }
}

// ---- O projection GEMM (fp32 out, split W) ----
__global__ void __launch_bounds__(256, 2) gemm_o(
    const __half* __restrict__ Aa, const __half* __restrict__ Bh,
    const __half* __restrict__ Bl,
    const float* __restrict__ bias, float* __restrict__ C)
{
    extern __shared__ char smem[];
    const uint32_t sb = smem_u32(smem);
    const int tid = threadIdx.x;
    const int lane = tid & 31;
    const int wid = tid >> 5;
    const int wm = wid & 1;
    const int wn = wid >> 1;
    const int m0 = blockIdx.y * BM;
    const int n0 = blockIdx.x * BN;

    float acc[4][4][4];
#pragma unroll
    for (int i = 0; i < 4; i++)
#pragma unroll
        for (int j = 0; j < 4; j++)
#pragma unroll
            for (int q = 0; q < 4; q++) acc[i][j][q] = 0.f;

    gemm_mainloop<true>(sb, Aa + (size_t)m0 * E_, Bh + (size_t)n0 * E_,
                        Bl + (size_t)n0 * E_, E_, tid, lane, wm, wn, acc);

    const int g = lane >> 2;
    const int cq = lane & 3;
#pragma unroll
    for (int mi = 0; mi < 4; mi++) {
#pragma unroll
        for (int ni = 0; ni < 4; ni++) {
            const int col = n0 + wn * 32 + ni * 8 + cq * 2;
            const float b0 = bias[col];
            const float b1 = bias[col + 1];
#pragma unroll
            for (int h = 0; h < 2; h++) {
                const int row = m0 + wm * 64 + mi * 16 + g + h * 8;
                float2 v;
                v.x = acc[mi][ni][h * 2 + 0] + b0;
                v.y = acc[mi][ni][h * 2 + 1] + b1;
                *(float2*)(C + (size_t)row * E_ + col) = v;
            }
        }
    }
}

// =================================================================
// HMMA flash attention (R16, unchanged): 64 q-rows/CTA, 128 threads,
// Q in regs, 3-stage KV, mid-compute loads, exp2 softmax, ballot guard.
// =================================================================
#define QSTR 272
#define AT_STG  (2 * 64 * QSTR)        // 34816 (K, V)
#define AT_K    0
#define AT_V    (64 * QSTR)
#define AT_SMEM (3 * AT_STG)           // 104448 -> 2 CTAs/SM

__device__ __forceinline__ void attn_load_kv(uint32_t sb, int stage, int b, int hk,
                                             int kt, const __half* kf,
                                             const __half* vf, int tid)
{
    const uint32_t base = sb + stage * AT_STG;
    const size_t rowg = (size_t)(b * N_ + kt * 64);
#pragma unroll
    for (int it = 0; it < 16; it++) {
        int idx = tid + it * 128;              // 0..2047
        int buf = idx >> 10;                   // 0: K, 1: V
        int r = (idx & 1023) >> 4;             // 0..63
        int c = idx & 15;
        uint32_t dst = base + (buf ? AT_V : AT_K) + r * QSTR + c * 16;
        const __half* src = buf ? vf : kf;
        cp16(dst, src + (rowg + r) * KVE_ + hk * D_ + c * 8);
    }
}

__global__ void __launch_bounds__(128, 2) attn_mma(
    const __half* __restrict__ qh, const __half* __restrict__ ql,
    const __half* __restrict__ kf, const __half* __restrict__ vf,
    __half* __restrict__ ao,
    const int* __restrict__ causal_p)
{
    extern __shared__ char smem[];
    const uint32_t sb = smem_u32(smem);
    const int tid = threadIdx.x;
    const int lane = tid & 31;
    const int wid = tid >> 5;
    const int qt = (int)(gridDim.x - 1 - blockIdx.x);  // heavy tiles first
    const int bh = blockIdx.y;
    const int b  = bh >> 4;
    const int hq = bh & 15;
    const int hk = hq >> 2;
    const int wr = wid * 16;
    const int g = lane >> 2;
    const int cq = lane & 3;
    const bool causal = (causal_p[0] != 0);
    const float l2s = 0.12751875732437f;  // log2(e)/sqrt(128)

    const uint32_t a_off = (uint32_t)((lane & 15) * QSTR + (lane >> 4) * 16);
    const uint32_t b_off = (uint32_t)(((lane & 7) + (lane >> 4) * 8) * QSTR
                                      + ((lane >> 3) & 1) * 16);

    const int ktend = causal ? (qt + 1) : (N_ / 64);

    {
        const size_t rowg = (size_t)(b * N_ + qt * 64);
#pragma unroll
        for (int it = 0; it < 16; it++) {
            int idx = tid + it * 128;
            int buf = idx >> 10;
            int r = (idx & 1023) >> 4;
            int c = idx & 15;
            uint32_t dst = sb + buf * AT_STG + r * QSTR + c * 16;
            const __half* src = buf ? ql : qh;
            cp16(dst, src + (rowg + r) * E_ + hq * D_ + c * 8);
        }
    }
    CP_COMMIT();
    CP_WAIT(0);
    __syncthreads();

    uint32_t qHf[8][4], qLf[8][4];
#pragma unroll
    for (int ks = 0; ks < 8; ks++) {
        ldm_x4(qHf[ks], sb + 0 * AT_STG + wr * QSTR + ks * 32 + a_off);
        ldm_x4(qLf[ks], sb + 1 * AT_STG + wr * QSTR + ks * 32 + a_off);
    }
    __syncthreads();

    attn_load_kv(sb, 0, b, hk, 0, kf, vf, tid);
    CP_COMMIT();
    if (1 < ktend) {
        attn_load_kv(sb, 1, b, hk, 1, kf, vf, tid);
        CP_COMMIT();
    }

    float m_i[2] = { -1e30f, -1e30f };
    float l_i[2] = { 0.f, 0.f };
    float o[16][4];
#pragma unroll
    for (int i = 0; i < 16; i++)
#pragma unroll
        for (int j = 0; j < 4; j++) o[i][j] = 0.f;

    for (int kt = 0; kt < ktend; kt++) {
        if (kt + 1 < ktend) { CP_WAIT(1); } else { CP_WAIT(0); }
        __syncthreads();

        const int cst = kt % 3;
        const uint32_t Kb = sb + cst * AT_STG + AT_K;
        const uint32_t Vb = sb + cst * AT_STG + AT_V;

        float s[8][4];
#pragma unroll
        for (int i = 0; i < 8; i++)
#pragma unroll
            for (int j = 0; j < 4; j++) s[i][j] = 0.f;

#pragma unroll
        for (int ks = 0; ks < 8; ks++) {
            const uint32_t kb = ks * 32;
#pragma unroll
            for (int t = 0; t < 4; t++) {
                uint32_t b4[4];
                ldm_x4(b4, Kb + (t * 16) * QSTR + kb + b_off);
                mma_f16(s[2 * t],     qHf[ks], b4[0], b4[1]);
                mma_f16(s[2 * t],     qLf[ks], b4[0], b4[1]);
                mma_f16(s[2 * t + 1], qHf[ks], b4[2], b4[3]);
                mma_f16(s[2 * t + 1], qLf[ks], b4[2], b4[3]);
            }
        }

        const int row0 = qt * 64 + wr + g;
        if (causal && (kt * 64 + 63 > qt * 64 + wr)) {
            const int col0 = kt * 64 + 2 * cq;
#pragma unroll
            for (int ni = 0; ni < 8; ni++)
#pragma unroll
                for (int j = 0; j < 4; j++) {
                    int row = row0 + (j >> 1) * 8;
                    int col = col0 + ni * 8 + (j & 1);
                    if (col > row) s[ni][j] = -1e30f;
                }
        }

#pragma unroll
        for (int h = 0; h < 2; h++) {
            float rm = -1e30f;
#pragma unroll
            for (int ni = 0; ni < 8; ni++)
                rm = fmaxf(rm, fmaxf(s[ni][2 * h], s[ni][2 * h + 1]));
            rm = fmaxf(rm, __shfl_xor_sync(0xffffffffu, rm, 1));
            rm = fmaxf(rm, __shfl_xor_sync(0xffffffffu, rm, 2));
            const float mold = m_i[h];
            const float mn = fmaxf(mold, rm);
            m_i[h] = mn;
            float rs = 0.f;
#pragma unroll
            for (int ni = 0; ni < 8; ni++) {
                float e0 = exp2f((s[ni][2 * h]     - mn) * l2s);
                float e1 = exp2f((s[ni][2 * h + 1] - mn) * l2s);
                s[ni][2 * h] = e0; s[ni][2 * h + 1] = e1;
                rs += e0 + e1;
            }
            rs += __shfl_xor_sync(0xffffffffu, rs, 1);
            rs += __shfl_xor_sync(0xffffffffu, rs, 2);
            const float alpha = exp2f((mold - mn) * l2s);
            l_i[h] = l_i[h] * alpha + rs;
            if (__ballot_sync(0xffffffffu, mold != mn)) {
#pragma unroll
                for (int np = 0; np < 16; np++) {
                    o[np][2 * h]     *= alpha;
                    o[np][2 * h + 1] *= alpha;
                }
            }
        }

        if (kt + 2 < ktend) {
            attn_load_kv(sb, (kt + 2) % 3, b, hk, kt + 2, kf, vf, tid);
            CP_COMMIT();
        }

#pragma unroll
        for (int ks = 0; ks < 4; ks++) {
            uint32_t aPh[4], aPl[4];
#pragma unroll
            for (int q = 0; q < 4; q++) {
                const int ni = 2 * ks + (q >> 1);
                const int j0 = (q & 1) * 2;
                float e0 = s[ni][j0], e1 = s[ni][j0 + 1];
                __half2 hh = __floats2half2_rn(e0, e1);
                aPh[q] = *(uint32_t*)&hh;
                float2 hf = __half22float2(hh);
                __half2 ll = __floats2half2_rn(e0 - hf.x, e1 - hf.y);
                aPl[q] = *(uint32_t*)&ll;
            }
#pragma unroll
            for (int np = 0; np < 8; np++) {
                uint32_t bv[4];
                ldm_x4_t(bv, Vb + (ks * 16) * QSTR + np * 32 + a_off);
                mma_f16(o[2 * np],     aPh, bv[0], bv[1]);
                mma_f16(o[2 * np],     aPl, bv[0], bv[1]);
                mma_f16(o[2 * np + 1], aPh, bv[2], bv[3]);
                mma_f16(o[2 * np + 1], aPl, bv[2], bv[3]);
            }
        }
    }

    const float inv0 = 1.f / l_i[0];
    const float inv1 = 1.f / l_i[1];
    const size_t rowa = (size_t)(b * N_ + qt * 64 + wr + g);
    const int colb = hq * D_ + 2 * cq;
#pragma unroll
    for (int np = 0; np < 16; np++) {
        *(__half2*)(ao + rowa * E_ + colb + np * 8) =
            __floats2half2_rn(o[np][0] * inv0, o[np][1] * inv0);
        *(__half2*)(ao + (rowa + 8) * E_ + colb + np * 8) =
            __floats2half2_rn(o[np][2] * inv1, o[np][3] * inv1);
    }
}

// =================================================================
extern "C" void kernel_launch(void* const* d_in, const int* in_sizes, int n_in,
                              void* d_out, int out_size)
{
    const float* query = (const float*)d_in[0];
    const float* key   = (const float*)d_in[1];
    const float* value = (const float*)d_in[2];
    const float* Wq = (const float*)d_in[3];
    const float* bq = (const float*)d_in[4];
    const float* Wk = (const float*)d_in[5];
    const float* bk = (const float*)d_in[6];
    const float* Wv = (const float*)d_in[7];
    const float* bv = (const float*)d_in[8];
    const float* Wo = (const float*)d_in[9];
    const float* bo = (const float*)d_in[10];
    const int* is_causal = (const int*)d_in[11];
    float* out = (float*)d_out;

    __half *sq, *sk, *sv;
    __half *wqh, *wql, *wkh, *wvh, *woh, *wol;
    __half *qhp, *qlp, *kfp, *vfp, *afp;
    cudaGetSymbolAddress((void**)&sq, s_q);
    cudaGetSymbolAddress((void**)&sk, s_k);
    cudaGetSymbolAddress((void**)&sv, s_v);
    cudaGetSymbolAddress((void**)&wqh, w_q_h);  cudaGetSymbolAddress((void**)&wql, w_q_l);
    cudaGetSymbolAddress((void**)&wkh, w_k_h);
    cudaGetSymbolAddress((void**)&wvh, w_v_h);
    cudaGetSymbolAddress((void**)&woh, w_o_h);  cudaGetSymbolAddress((void**)&wol, w_o_l);
    cudaGetSymbolAddress((void**)&qhp, q_h16);  cudaGetSymbolAddress((void**)&qlp, q_l16);
    cudaGetSymbolAddress((void**)&kfp, k_f16);  cudaGetSymbolAddress((void**)&vfp, v_f16);
    cudaGetSymbolAddress((void**)&afp, a_f16);

    // ---- fused converts (7 segments, one launch) ----
    const int actN4 = (MR_ * E_) / 4;
    const int wqN4  = (E_ * E_) / 4;
    const int wkN4  = (KVE_ * E_) / 4;
    SplitSegs segs;
    segs.x[0] = query; segs.hi[0] = sq;  segs.lo[0] = nullptr;
    segs.x[1] = key;   segs.hi[1] = sk;  segs.lo[1] = nullptr;
    segs.x[2] = value; segs.hi[2] = sv;  segs.lo[2] = nullptr;
    segs.x[3] = Wq;    segs.hi[3] = wqh; segs.lo[3] = wql;
    segs.x[4] = Wk;    segs.hi[4] = wkh; segs.lo[4] = nullptr;   // single fp16
    segs.x[5] = Wv;    segs.hi[5] = wvh; segs.lo[5] = nullptr;   // single fp16
    segs.x[6] = Wo;    segs.hi[6] = woh; segs.lo[6] = wol;
    int nb = 0;
    const int segBlocks[7] = { actN4/256, actN4/256, actN4/256,
                               wqN4/256, wkN4/256, wkN4/256, wqN4/256 };
    for (int s = 0; s < 7; s++) { nb += segBlocks[s]; segs.blk_end[s] = nb; }
    split_fused<<<nb, 256>>>(segs);

    // ---- fused Q/K/V projection GEMMs ----
    cudaFuncSetAttribute(gemm_qkv, cudaFuncAttributeMaxDynamicSharedMemorySize, GSMEM);
    cudaFuncSetAttribute(gemm_o,   cudaFuncAttributeMaxDynamicSharedMemorySize, GSMEM);
    const int qkvBlocks = (E_ / BN) * (MR_ / BM) + 2 * (KVE_ / BN) * (MR_ / BM); // 768
    gemm_qkv<<<qkvBlocks, 256, GSMEM>>>(
        sq, wqh, wql, bq, qhp, qlp,
        sk, wkh, bk, kfp,
        sv, wvh, bv, vfp);

    // ---- HMMA flash attention ----
    cudaFuncSetAttribute(attn_mma, cudaFuncAttributeMaxDynamicSharedMemorySize, AT_SMEM);
    attn_mma<<<dim3(N_ / 64, B_ * HQ_), 128, AT_SMEM>>>(
        qhp, qlp, kfp, vfp, afp, is_causal);

    // ---- O projection (fp32 out) ----
    gemm_o<<<dim3(E_ / BN, MR_ / BM), 256, GSMEM>>>(afp, woh, wol, bo, out);
}